// round 2
// baseline (speedup 1.0000x reference)
#include <cuda_runtime.h>

#define NT     256
#define TLEN   512
#define LD     36     // padded leading dim, 32-col matrices
#define LDA    68     // augmented GJ matrix leading dim
#define LDCT   20     // C-transpose leading dim (16 cols + pad)

// ---- shared memory layout (float offsets, all multiples of 4) ----
#define O_SAM  0       // 8*32*32 A mixture components (dense, stride 32)
#define O_SBM  8192    // 8*32*32 B components
#define O_SCM  16384   // 8*16*32 C components
#define O_A    20480   // 32xLD   A_t
#define O_ATR  21632   // 32xLD   A_t^T
#define O_CM   22784   // 16xLD   C_t
#define O_CTR  23360   // 32xLDCT C_t^T
#define O_ZC   24000   // 32xLD   covariance state (P filt / Ps)
#define O_TMP  25152   // 32xLD   scratch (B mixture / D)
#define O_PP   26304   // 32xLD   scratch (A*zc / P_pred / W)
#define O_CPM  27456   // 16xLD   M = C*P
#define O_AUG  28032   // 32xLDA  GJ augmented matrix
#define O_FCS  30208   // 32xLD   filtered cov reload (backward)
#define O_FMS  31360   // 32      filtered mean reload
#define O_ZM   31392   // 32      mean state
#define O_ZM2  31424   // 32      predicted mean scratch
#define O_AL   31456   // 8       alpha
#define O_SU   31464   // 32      u vector
#define O_BU   31496   // 32      (spare)
#define O_SA   31528   // 16      observation
#define O_AP   31544   // 16      a_pred
#define O_DZ   31560   // 32      innovation / zs residual
#define O_FCL  31592   // 32      GJ pivot column
#define O_PRW  31624   // 64      GJ pivot row
#define O_PV   31688   // 4       pivot inverse
#define O_QD   31692   // 32      diag Q
#define O_RD   31724   // 16      diag R
#define SMEM_FLOATS 31740

#define FMA4(acc, s, v) \
    acc.x = fmaf((s), (v).x, acc.x); acc.y = fmaf((s), (v).y, acc.y); \
    acc.z = fmaf((s), (v).z, acc.z); acc.w = fmaf((s), (v).w, acc.w);

__global__ __launch_bounds__(NT, 1)
void lgssm_kernel(const float* __restrict__ g_a,   const float* __restrict__ g_alpha,
                  const float* __restrict__ g_u,   const float* __restrict__ g_A,
                  const float* __restrict__ g_B,   const float* __restrict__ g_C,
                  const float* __restrict__ g_lQ,  const float* __restrict__ g_lR,
                  const float* __restrict__ g_z0m, const float* __restrict__ g_z0lv,
                  float* __restrict__ out)
{
    extern __shared__ float sh[];
    float* sAm  = sh + O_SAM;
    float* sBm  = sh + O_SBM;
    float* sCm  = sh + O_SCM;
    float* pA   = sh + O_A;
    float* pAtr = sh + O_ATR;
    float* pCm  = sh + O_CM;
    float* pCtr = sh + O_CTR;
    float* zc   = sh + O_ZC;
    float* tmpM = sh + O_TMP;
    float* pPp  = sh + O_PP;
    float* pCPm = sh + O_CPM;
    float* pAug = sh + O_AUG;
    float* fcS  = sh + O_FCS;
    float* fmS  = sh + O_FMS;
    float* zm   = sh + O_ZM;
    float* zm2  = sh + O_ZM2;
    float* al   = sh + O_AL;
    float* su   = sh + O_SU;
    float* sa   = sh + O_SA;
    float* apred= sh + O_AP;
    float* dz   = sh + O_DZ;
    float* fcol = sh + O_FCL;
    float* prow = sh + O_PRW;
    float* pv   = sh + O_PV;
    float* qd   = sh + O_QD;
    float* rd   = sh + O_RD;

    const int tid = threadIdx.x;
    const int b   = blockIdx.x;
    const int i8  = tid >> 3;          // 0..31 row
    const int j8  = (tid & 7) << 2;    // 0,4,...,28 col base

    // preload constant matrices + diag noise
    for (int idx = tid; idx < 8192; idx += NT) sAm[idx] = g_A[idx];
    for (int idx = tid; idx < 8192; idx += NT) sBm[idx] = g_B[idx];
    for (int idx = tid; idx < 4096; idx += NT) sCm[idx] = g_C[idx];
    if (tid < 32) qd[tid] = expf(g_lQ[tid]);
    if (tid < 16) rd[tid] = expf(g_lR[tid]);
    // (ordered by the first __syncthreads below)

    // =============== FORWARD FILTER ===============
    #pragma unroll 1
    for (int t = 0; t < TLEN; ++t) {
        const size_t ib = (size_t)b * TLEN + t;
        if (tid < 8)  al[tid] = g_alpha[ib * 8  + tid];
        if (tid < 32) su[tid] = g_u    [ib * 32 + tid];
        if (tid < 16) sa[tid] = g_a    [ib * 16 + tid];
        if (t == 0) {
            if (tid < 32) zm[tid] = g_z0m[tid];
            float4 v = make_float4(0.f, 0.f, 0.f, 0.f);
            int d = i8 - j8;
            if (d >= 0 && d < 4) ((float*)&v)[d] = expf(g_z0lv[i8]);
            *(float4*)(zc + i8 * LD + j8) = v;
        }
        __syncthreads();

        // ---- form mixture matrices A, A^T, B(tmpM), C, C^T ----
        {
            float4 aa = make_float4(0.f,0.f,0.f,0.f);
            float4 bb = make_float4(0.f,0.f,0.f,0.f);
            #pragma unroll
            for (int k = 0; k < 8; ++k) {
                const float w = al[k];
                float4 m = *(const float4*)(sAm + k * 1024 + i8 * 32 + j8);
                FMA4(aa, w, m);
                m = *(const float4*)(sBm + k * 1024 + i8 * 32 + j8);
                FMA4(bb, w, m);
            }
            *(float4*)(pA + i8 * LD + j8) = aa;
            pAtr[(j8 + 0) * LD + i8] = aa.x;
            pAtr[(j8 + 1) * LD + i8] = aa.y;
            pAtr[(j8 + 2) * LD + i8] = aa.z;
            pAtr[(j8 + 3) * LD + i8] = aa.w;
            *(float4*)(tmpM + i8 * LD + j8) = bb;
            if (i8 < 16) {
                float4 cc = make_float4(0.f,0.f,0.f,0.f);
                #pragma unroll
                for (int k = 0; k < 8; ++k) {
                    const float w = al[k];
                    float4 m = *(const float4*)(sCm + k * 512 + i8 * 32 + j8);
                    FMA4(cc, w, m);
                }
                *(float4*)(pCm + i8 * LD + j8) = cc;
                pCtr[(j8 + 0) * LDCT + i8] = cc.x;
                pCtr[(j8 + 1) * LDCT + i8] = cc.y;
                pCtr[(j8 + 2) * LDCT + i8] = cc.z;
                pCtr[(j8 + 3) * LDCT + i8] = cc.w;
            }
        }
        __syncthreads();

        if (t > 0) {
            // ---- predict: zm2 = A zm + B u ; Pp = A zc ----
            if (tid < 32) {
                float s = 0.f;
                #pragma unroll 8
                for (int k = 0; k < 32; ++k) s = fmaf(tmpM[tid * LD + k], su[k], s);
                #pragma unroll 8
                for (int k = 0; k < 32; ++k) s = fmaf(pA[tid * LD + k], zm[k], s);
                zm2[tid] = s;
            }
            {
                float4 acc = make_float4(0.f,0.f,0.f,0.f);
                #pragma unroll 8
                for (int k = 0; k < 32; ++k) {
                    float a = pA[i8 * LD + k];
                    float4 vv = *(const float4*)(zc + k * LD + j8);
                    FMA4(acc, a, vv);
                }
                *(float4*)(pPp + i8 * LD + j8) = acc;
            }
            __syncthreads();
            // ---- zc = Pp A^T + Q ; zm = zm2 ----
            {
                float4 acc = make_float4(0.f,0.f,0.f,0.f);
                #pragma unroll 8
                for (int k = 0; k < 32; ++k) {
                    float a = pPp[i8 * LD + k];
                    float4 vv = *(const float4*)(pAtr + k * LD + j8);
                    FMA4(acc, a, vv);
                }
                int d = i8 - j8;
                if (d >= 0 && d < 4) ((float*)&acc)[d] += qd[i8];
                *(float4*)(zc + i8 * LD + j8) = acc;
            }
            if (tid < 32) zm[tid] = zm2[tid];
            __syncthreads();
        }

        // ---- measurement update: apred = C zm ; M = C zc (CPm) ----
        if (i8 < 16) {
            if (tid < 16) {
                float s = 0.f;
                #pragma unroll 8
                for (int k = 0; k < 32; ++k) s = fmaf(pCm[tid * LD + k], zm[k], s);
                apred[tid] = s;
            }
            float4 acc = make_float4(0.f,0.f,0.f,0.f);
            #pragma unroll 8
            for (int k = 0; k < 32; ++k) {
                float c = pCm[i8 * LD + k];
                float4 vv = *(const float4*)(zc + k * LD + j8);
                FMA4(acc, c, vv);
            }
            *(float4*)(pCPm + i8 * LD + j8) = acc;
        }
        __syncthreads();

        // ---- build aug = [S | M] (16x48), S = M C^T + R ; dz = a - apred ----
        if (tid < 64) {
            int i = tid >> 2, j0 = (tid & 3) << 2;
            float4 acc = make_float4(0.f,0.f,0.f,0.f);
            #pragma unroll 8
            for (int k = 0; k < 32; ++k) {
                float mv = pCPm[i * LD + k];
                float4 vv = *(const float4*)(pCtr + k * LDCT + j0);
                FMA4(acc, mv, vv);
            }
            int d = i - j0;
            if (d >= 0 && d < 4) ((float*)&acc)[d] += rd[i];
            *(float4*)(pAug + i * LDA + j0) = acc;
        }
        if (tid >= 64 && tid < 80) dz[tid - 64] = sa[tid - 64] - apred[tid - 64];
        if (i8 < 16)
            *(float4*)(pAug + i8 * LDA + 16 + j8) = *(const float4*)(pCPm + i8 * LD + j8);
        __syncthreads();

        // ---- Gauss-Jordan 16 pivots -> right half = Kg^T = S^-1 M ----
        #pragma unroll 1
        for (int p = 0; p < 16; ++p) {
            if (tid < 16) fcol[tid] = pAug[tid * LDA + p];
            else if (tid < 64) prow[tid - 16] = pAug[p * LDA + (tid - 16)];
            else if (tid == 64) pv[0] = 1.f / pAug[p * LDA + p];
            __syncthreads();
            {
                int i = tid >> 4, jb = tid & 15;
                float f = fcol[i], pvv = pv[0];
                #pragma unroll
                for (int c = 0; c < 3; ++c) {
                    int j = jb + (c << 4);
                    float pr = prow[j] * pvv;
                    pAug[i * LDA + j] = (i == p) ? pr : fmaf(-f, pr, pAug[i * LDA + j]);
                }
            }
            __syncthreads();
        }

        // ---- apply update, write filtered output ----
        {
            const size_t ob = ib * 2112;
            if (tid < 32) {
                float s = 0.f;
                #pragma unroll
                for (int r = 0; r < 16; ++r) s = fmaf(pAug[r * LDA + 16 + tid], dz[r], s);
                float nm = zm[tid] + s;
                zm[tid] = nm;
                out[ob + tid] = nm;
                if (t == TLEN - 1) out[ob + 1056 + tid] = nm;
            }
            float4 acc = *(const float4*)(zc + i8 * LD + j8);
            #pragma unroll
            for (int r = 0; r < 16; ++r) {
                float kv = pAug[r * LDA + 16 + i8];
                float4 mv = *(const float4*)(pCPm + r * LD + j8);
                acc.x = fmaf(-kv, mv.x, acc.x); acc.y = fmaf(-kv, mv.y, acc.y);
                acc.z = fmaf(-kv, mv.z, acc.z); acc.w = fmaf(-kv, mv.w, acc.w);
            }
            *(float4*)(zc + i8 * LD + j8) = acc;
            *(float4*)(out + ob + 32 + i8 * 32 + j8) = acc;
            if (t == TLEN - 1) *(float4*)(out + ob + 1088 + i8 * 32 + j8) = acc;
        }
    }

    // =============== BACKWARD RTS SMOOTHER ===============
    // state: zm = zs, zc = Ps (currently filtered values at t = T-1)
    #pragma unroll 1
    for (int t = TLEN - 2; t >= 0; --t) {
        __syncthreads();  // protect fcS (read last iter) before reload
        const size_t ibn = (size_t)b * TLEN + (t + 1);
        const size_t ib  = (size_t)b * TLEN + t;
        const size_t ob  = ib * 2112;
        if (tid < 8)  al[tid] = g_alpha[ibn * 8 + tid];
        if (tid < 32) { su[tid] = g_u[ibn * 32 + tid]; fmS[tid] = out[ob + tid]; }
        *(float4*)(fcS + i8 * LD + j8) = *(const float4*)(out + ob + 32 + i8 * 32 + j8);
        __syncthreads();

        // ---- mixtures A, A^T, B(tmpM) for step t+1 ----
        {
            float4 aa = make_float4(0.f,0.f,0.f,0.f);
            float4 bb = make_float4(0.f,0.f,0.f,0.f);
            #pragma unroll
            for (int k = 0; k < 8; ++k) {
                const float w = al[k];
                float4 m = *(const float4*)(sAm + k * 1024 + i8 * 32 + j8);
                FMA4(aa, w, m);
                m = *(const float4*)(sBm + k * 1024 + i8 * 32 + j8);
                FMA4(bb, w, m);
            }
            *(float4*)(pA + i8 * LD + j8) = aa;
            pAtr[(j8 + 0) * LD + i8] = aa.x;
            pAtr[(j8 + 1) * LD + i8] = aa.y;
            pAtr[(j8 + 2) * LD + i8] = aa.z;
            pAtr[(j8 + 3) * LD + i8] = aa.w;
            *(float4*)(tmpM + i8 * LD + j8) = bb;
        }
        __syncthreads();

        // ---- dz = zs - (A fm + B u) ; N = A fc -> aug right half ----
        if (tid < 32) {
            float s = 0.f;
            #pragma unroll 8
            for (int k = 0; k < 32; ++k) s = fmaf(tmpM[tid * LD + k], su[k], s);
            #pragma unroll 8
            for (int k = 0; k < 32; ++k) s = fmaf(pA[tid * LD + k], fmS[k], s);
            dz[tid] = zm[tid] - s;
        }
        {
            float4 acc = make_float4(0.f,0.f,0.f,0.f);
            #pragma unroll 8
            for (int k = 0; k < 32; ++k) {
                float a = pA[i8 * LD + k];
                float4 vv = *(const float4*)(fcS + k * LD + j8);
                FMA4(acc, a, vv);
            }
            *(float4*)(pAug + i8 * LDA + 32 + j8) = acc;
        }
        __syncthreads();

        // ---- P_pred = N A^T + Q -> Pp and aug left half ----
        {
            float4 acc = make_float4(0.f,0.f,0.f,0.f);
            #pragma unroll 8
            for (int k = 0; k < 32; ++k) {
                float a = pAug[i8 * LDA + 32 + k];
                float4 vv = *(const float4*)(pAtr + k * LD + j8);
                FMA4(acc, a, vv);
            }
            int d = i8 - j8;
            if (d >= 0 && d < 4) ((float*)&acc)[d] += qd[i8];
            *(float4*)(pPp + i8 * LD + j8) = acc;
            *(float4*)(pAug + i8 * LDA + j8) = acc;
        }
        __syncthreads();

        // ---- Gauss-Jordan 32 pivots -> right half Y = Ppred^-1 N = J^T ----
        #pragma unroll 1
        for (int p = 0; p < 32; ++p) {
            if (tid < 32) fcol[tid] = pAug[tid * LDA + p];
            else if (tid < 96) prow[tid - 32] = pAug[p * LDA + (tid - 32)];
            else if (tid == 96) pv[0] = 1.f / pAug[p * LDA + p];
            __syncthreads();
            {
                int i = tid >> 3, jb = tid & 7;
                float f = fcol[i], pvv = pv[0];
                #pragma unroll
                for (int c = 0; c < 8; ++c) {
                    int j = jb + (c << 3);
                    float pr = prow[j] * pvv;
                    pAug[i * LDA + j] = (i == p) ? pr : fmaf(-f, pr, pAug[i * LDA + j]);
                }
            }
            __syncthreads();
        }

        // ---- zs = fm + Y^T dz (write sm) ; D = Ps - Ppred -> tmpM ----
        if (tid < 32) {
            float s = 0.f;
            #pragma unroll 8
            for (int r = 0; r < 32; ++r) s = fmaf(pAug[r * LDA + 32 + tid], dz[r], s);
            float nm = fmS[tid] + s;
            zm[tid] = nm;
            out[ob + 1056 + tid] = nm;
        }
        {
            float4 a = *(const float4*)(zc + i8 * LD + j8);
            float4 p4 = *(const float4*)(pPp + i8 * LD + j8);
            a.x -= p4.x; a.y -= p4.y; a.z -= p4.z; a.w -= p4.w;
            *(float4*)(tmpM + i8 * LD + j8) = a;
        }
        __syncthreads();

        // ---- W = D Y -> Pp ----
        {
            float4 acc = make_float4(0.f,0.f,0.f,0.f);
            #pragma unroll 8
            for (int k = 0; k < 32; ++k) {
                float dv = tmpM[i8 * LD + k];
                float4 vv = *(const float4*)(pAug + k * LDA + 32 + j8);
                FMA4(acc, dv, vv);
            }
            *(float4*)(pPp + i8 * LD + j8) = acc;
        }
        __syncthreads();

        // ---- Ps = fc + Y^T W -> zc, write sc ----
        {
            float4 acc = *(const float4*)(fcS + i8 * LD + j8);
            #pragma unroll 8
            for (int k = 0; k < 32; ++k) {
                float yv = pAug[k * LDA + 32 + i8];
                float4 wv = *(const float4*)(pPp + k * LD + j8);
                FMA4(acc, yv, wv);
            }
            *(float4*)(zc + i8 * LD + j8) = acc;
            *(float4*)(out + ob + 1088 + i8 * 32 + j8) = acc;
        }
    }
}

extern "C" void kernel_launch(void* const* d_in, const int* in_sizes, int n_in,
                              void* d_out, int out_size) {
    const float* g_a    = (const float*)d_in[0];
    const float* g_alpha= (const float*)d_in[1];
    const float* g_u    = (const float*)d_in[2];
    const float* g_A    = (const float*)d_in[3];
    const float* g_B    = (const float*)d_in[4];
    const float* g_C    = (const float*)d_in[5];
    const float* g_lQ   = (const float*)d_in[6];
    const float* g_lR   = (const float*)d_in[7];
    const float* g_z0m  = (const float*)d_in[8];
    const float* g_z0lv = (const float*)d_in[9];
    float* out = (float*)d_out;
    int B = in_sizes[0] / (TLEN * 16);
    size_t smem = SMEM_FLOATS * sizeof(float);
    cudaFuncSetAttribute(lgssm_kernel, cudaFuncAttributeMaxDynamicSharedMemorySize, (int)smem);
    lgssm_kernel<<<B, NT, smem>>>(g_a, g_alpha, g_u, g_A, g_B, g_C,
                                  g_lQ, g_lR, g_z0m, g_z0lv, out);
}

// round 3
// speedup vs baseline: 1.9048x; 1.9048x over previous
#include <cuda_runtime.h>

#define NT     256
#define TLEN   512
#define LD     36     // padded leading dim, 32-col matrices
#define LDA    68     // augmented GJ matrix leading dim
#define LDCT   20     // C-transpose leading dim

// ---- shared memory layout (float offsets) ----
#define O_SAM  0       // 8*32*32 A components
#define O_SBM  8192    // 8*32*32 B components
#define O_SCM  16384   // 8*16*32 C components
#define O_A    20480   // 32xLD   A_t
#define O_ATR  21632   // 32xLD   A_t^T
#define O_CM   22784   // 16xLD   C_t
#define O_CTR  23360   // 32xLDCT C_t^T
#define O_ZC   24000   // 32xLD   covariance state
#define O_TMP  25152   // 32xLD   scratch (B mixture / D)
#define O_PP   26304   // 32xLD   scratch (A*zc / P_pred / W)
#define O_CPM  27456   // 16xLD   M = C*P
#define O_AUG0 28032   // 32xLDA  GJ buffer 0
#define O_AUG1 30208   // 32xLDA  GJ buffer 1
#define O_FCS  32384   // 2 x 32xLD  filtered cov (parity)
#define O_FMS  34688   // 2 x 32     filtered mean (parity)
#define O_ZM   34752   // 32
#define O_ZM2  34784   // 32
#define O_AL   34816   // 2 x 8
#define O_SU   34832   // 2 x 32
#define O_SA   34896   // 2 x 16
#define O_AP   34928   // 16
#define O_DZ   34944   // 32
#define O_QD   34976   // 32
#define O_RD   35008   // 16
#define SMEM_FLOATS 35024

#define FMA4(acc, s, v) \
    acc.x = fmaf((s), (v).x, acc.x); acc.y = fmaf((s), (v).y, acc.y); \
    acc.z = fmaf((s), (v).z, acc.z); acc.w = fmaf((s), (v).w, acc.w);

__global__ __launch_bounds__(NT, 1)
void lgssm_kernel(const float* __restrict__ g_a,   const float* __restrict__ g_alpha,
                  const float* __restrict__ g_u,   const float* __restrict__ g_A,
                  const float* __restrict__ g_B,   const float* __restrict__ g_C,
                  const float* __restrict__ g_lQ,  const float* __restrict__ g_lR,
                  const float* __restrict__ g_z0m, const float* __restrict__ g_z0lv,
                  float* __restrict__ out)
{
    extern __shared__ float sh[];
    float* sAm  = sh + O_SAM;
    float* sBm  = sh + O_SBM;
    float* sCm  = sh + O_SCM;
    float* pA   = sh + O_A;
    float* pAtr = sh + O_ATR;
    float* pCm  = sh + O_CM;
    float* pCtr = sh + O_CTR;
    float* zc   = sh + O_ZC;
    float* tmpM = sh + O_TMP;
    float* pPp  = sh + O_PP;
    float* pCPm = sh + O_CPM;
    float* aug0 = sh + O_AUG0;
    float* aug1 = sh + O_AUG1;
    float* fcS  = sh + O_FCS;   // + parity*1152
    float* fmS  = sh + O_FMS;   // + parity*32
    float* zm   = sh + O_ZM;
    float* zm2  = sh + O_ZM2;
    float* alB  = sh + O_AL;    // + parity*8
    float* suB  = sh + O_SU;    // + parity*32
    float* saB  = sh + O_SA;    // + parity*16
    float* apred= sh + O_AP;
    float* dz   = sh + O_DZ;
    float* qd   = sh + O_QD;
    float* rd   = sh + O_RD;

    const int tid = threadIdx.x;
    const int b   = blockIdx.x;
    const int i8  = tid >> 3;          // 0..31 row
    const int j8  = (tid & 7) << 2;    // col base 0,4..28
    const int g16i = tid >> 4, g16j = tid & 15;   // forward GJ map
    const int g8i  = tid >> 3, g8j  = tid & 7;    // backward GJ map

    // ---- preload constants, noise diagonals, t=0 inputs, init state ----
    for (int idx = tid; idx < 8192; idx += NT) sAm[idx] = g_A[idx];
    for (int idx = tid; idx < 8192; idx += NT) sBm[idx] = g_B[idx];
    for (int idx = tid; idx < 4096; idx += NT) sCm[idx] = g_C[idx];
    if (tid < 32) qd[tid] = expf(g_lQ[tid]);
    if (tid < 16) rd[tid] = expf(g_lR[tid]);
    {
        const size_t ib0 = (size_t)b * TLEN;
        if (tid < 8)  alB[tid] = g_alpha[ib0 * 8  + tid];
        if (tid < 32) suB[tid] = g_u    [ib0 * 32 + tid];
        if (tid < 16) saB[tid] = g_a    [ib0 * 16 + tid];
        if (tid < 32) zm[tid] = g_z0m[tid];
        float4 v = make_float4(0.f, 0.f, 0.f, 0.f);
        int d = i8 - j8;
        if (d >= 0 && d < 4) ((float*)&v)[d] = expf(g_z0lv[i8]);
        *(float4*)(zc + i8 * LD + j8) = v;
    }
    __syncthreads();

    // =============== FORWARD FILTER ===============
    #pragma unroll 1
    for (int t = 0; t < TLEN; ++t) {
        const size_t ib = (size_t)b * TLEN + t;
        const int pb = t & 1, nb = pb ^ 1;
        const bool hasnext = (t + 1 < TLEN);

        // prefetch next step's inputs into registers (stored in P4)
        float pfa = 0.f, pfu = 0.f, pfo = 0.f;
        if (hasnext) {
            if (tid < 8)  pfa = g_alpha[(ib + 1) * 8  + tid];
            if (tid < 32) pfu = g_u    [(ib + 1) * 32 + tid];
            if (tid < 16) pfo = g_a    [(ib + 1) * 16 + tid];
        }

        // ---- P0: mixture matrices A, A^T, B(tmpM), C, C^T ----
        {
            const float* al = alB + pb * 8;
            float4 aa = make_float4(0.f,0.f,0.f,0.f);
            float4 bb = make_float4(0.f,0.f,0.f,0.f);
            #pragma unroll
            for (int k = 0; k < 8; ++k) {
                const float w = al[k];
                float4 m = *(const float4*)(sAm + k * 1024 + i8 * 32 + j8);
                FMA4(aa, w, m);
                m = *(const float4*)(sBm + k * 1024 + i8 * 32 + j8);
                FMA4(bb, w, m);
            }
            *(float4*)(pA + i8 * LD + j8) = aa;
            pAtr[(j8 + 0) * LD + i8] = aa.x;
            pAtr[(j8 + 1) * LD + i8] = aa.y;
            pAtr[(j8 + 2) * LD + i8] = aa.z;
            pAtr[(j8 + 3) * LD + i8] = aa.w;
            *(float4*)(tmpM + i8 * LD + j8) = bb;
            if (i8 < 16) {
                float4 cc = make_float4(0.f,0.f,0.f,0.f);
                #pragma unroll
                for (int k = 0; k < 8; ++k) {
                    const float w = al[k];
                    float4 m = *(const float4*)(sCm + k * 512 + i8 * 32 + j8);
                    FMA4(cc, w, m);
                }
                *(float4*)(pCm + i8 * LD + j8) = cc;
                pCtr[(j8 + 0) * LDCT + i8] = cc.x;
                pCtr[(j8 + 1) * LDCT + i8] = cc.y;
                pCtr[(j8 + 2) * LDCT + i8] = cc.z;
                pCtr[(j8 + 3) * LDCT + i8] = cc.w;
            }
        }
        __syncthreads();

        if (t > 0) {
            // ---- P1: zm2 = A zm + B u ; Pp = A zc ----
            if (tid < 32) {
                const float* su = suB + pb * 32;
                float s = 0.f;
                #pragma unroll 8
                for (int k = 0; k < 32; ++k) s = fmaf(tmpM[tid * LD + k], su[k], s);
                #pragma unroll 8
                for (int k = 0; k < 32; ++k) s = fmaf(pA[tid * LD + k], zm[k], s);
                zm2[tid] = s;
            }
            {
                float4 acc = make_float4(0.f,0.f,0.f,0.f);
                #pragma unroll 8
                for (int k = 0; k < 32; ++k) {
                    float a = pA[i8 * LD + k];
                    float4 vv = *(const float4*)(zc + k * LD + j8);
                    FMA4(acc, a, vv);
                }
                *(float4*)(pPp + i8 * LD + j8) = acc;
            }
            __syncthreads();
            // ---- P2: zc = Pp A^T + Q ; zm = zm2 ----
            {
                float4 acc = make_float4(0.f,0.f,0.f,0.f);
                #pragma unroll 8
                for (int k = 0; k < 32; ++k) {
                    float a = pPp[i8 * LD + k];
                    float4 vv = *(const float4*)(pAtr + k * LD + j8);
                    FMA4(acc, a, vv);
                }
                int d = i8 - j8;
                if (d >= 0 && d < 4) ((float*)&acc)[d] += qd[i8];
                *(float4*)(zc + i8 * LD + j8) = acc;
            }
            if (tid < 32) zm[tid] = zm2[tid];
            __syncthreads();
        }

        // ---- P3: apred = C zm ; M = C zc ----
        if (i8 < 16) {
            if (tid < 16) {
                float s = 0.f;
                #pragma unroll 8
                for (int k = 0; k < 32; ++k) s = fmaf(pCm[tid * LD + k], zm[k], s);
                apred[tid] = s;
            }
            float4 acc = make_float4(0.f,0.f,0.f,0.f);
            #pragma unroll 8
            for (int k = 0; k < 32; ++k) {
                float c = pCm[i8 * LD + k];
                float4 vv = *(const float4*)(zc + k * LD + j8);
                FMA4(acc, c, vv);
            }
            *(float4*)(pCPm + i8 * LD + j8) = acc;
        }
        __syncthreads();

        // ---- P4: aug0 = [S | M], dz = a - apred; store prefetched inputs ----
        if (tid < 64) {
            int i = tid >> 2, j0 = (tid & 3) << 2;
            float4 acc = make_float4(0.f,0.f,0.f,0.f);
            #pragma unroll 8
            for (int k = 0; k < 32; ++k) {
                float mv = pCPm[i * LD + k];
                float4 vv = *(const float4*)(pCtr + k * LDCT + j0);
                FMA4(acc, mv, vv);
            }
            int d = i - j0;
            if (d >= 0 && d < 4) ((float*)&acc)[d] += rd[i];
            *(float4*)(aug0 + i * LDA + j0) = acc;
        }
        if (tid >= 64 && tid < 80) dz[tid - 64] = saB[pb * 16 + (tid - 64)] - apred[tid - 64];
        if (i8 < 16)
            *(float4*)(aug0 + i8 * LDA + 16 + j8) = *(const float4*)(pCPm + i8 * LD + j8);
        if (hasnext) {
            if (tid < 8)  alB[nb * 8  + tid] = pfa;
            if (tid < 32) suB[nb * 32 + tid] = pfu;
            if (tid < 16) saB[nb * 16 + tid] = pfo;
        }
        __syncthreads();

        // ---- GJ: 16 pivots, 2 per phase, double-buffered (8 barriers) ----
        {
            float* Asrc = aug0; float* Adst = aug1;
            #pragma unroll 1
            for (int pp = 0; pp < 8; ++pp) {
                const int p = pp << 1, q = p | 1;
                float Mip = Asrc[g16i * LDA + p], Miq = Asrc[g16i * LDA + q];
                float Mpp = Asrc[p * LDA + p],   Mpq = Asrc[p * LDA + q];
                float Mqp = Asrc[q * LDA + p],   Mqq = Asrc[q * LDA + q];
                float inv1 = __fdividef(1.f, Mpp);
                float r1q  = Mpq * inv1;
                float inv2 = __fdividef(1.f, fmaf(-Mqp, r1q, Mqq));
                float E1iq = (g16i == p) ? r1q : fmaf(-Mip, r1q, Miq);
                #pragma unroll
                for (int c = 0; c < 3; ++c) {
                    int j = g16j + (c << 4);
                    float Mpj = Asrc[p * LDA + j];
                    float Mqj = Asrc[q * LDA + j];
                    float Mij = Asrc[g16i * LDA + j];
                    float r1j  = Mpj * inv1;
                    float E1ij = (g16i == p) ? r1j : fmaf(-Mip, r1j, Mij);
                    float r2j  = fmaf(-Mqp, r1j, Mqj) * inv2;
                    Adst[g16i * LDA + j] = (g16i == q) ? r2j : fmaf(-E1iq, r2j, E1ij);
                }
                float* tsw = Asrc; Asrc = Adst; Adst = tsw;
                __syncthreads();
            }
        }
        // result (Kg^T in cols 16..47) in aug0 after even number of swaps

        // ---- P13: apply measurement update, write filtered output ----
        {
            const size_t ob = ib * 2112;
            if (tid < 32) {
                float s = 0.f;
                #pragma unroll
                for (int r = 0; r < 16; ++r) s = fmaf(aug0[r * LDA + 16 + tid], dz[r], s);
                float nm = zm[tid] + s;
                zm[tid] = nm;
                out[ob + tid] = nm;
                if (t == TLEN - 1) out[ob + 1056 + tid] = nm;
            }
            float4 acc = *(const float4*)(zc + i8 * LD + j8);
            #pragma unroll
            for (int r = 0; r < 16; ++r) {
                float kv = aug0[r * LDA + 16 + i8];
                float4 mv = *(const float4*)(pCPm + r * LD + j8);
                acc.x = fmaf(-kv, mv.x, acc.x); acc.y = fmaf(-kv, mv.y, acc.y);
                acc.z = fmaf(-kv, mv.z, acc.z); acc.w = fmaf(-kv, mv.w, acc.w);
            }
            *(float4*)(zc + i8 * LD + j8) = acc;
            *(float4*)(out + ob + 32 + i8 * 32 + j8) = acc;
            if (t == TLEN - 1) *(float4*)(out + ob + 1088 + i8 * 32 + j8) = acc;
        }
        // no trailing barrier: next P0 touches disjoint smem; P0-end barrier orders zm/zc
    }

    // =============== BACKWARD RTS SMOOTHER ===============
    __syncthreads();
    {   // preload buffers for first backward iteration (t = TLEN-2)
        const size_t ibl = (size_t)b * TLEN + (TLEN - 1);
        const size_t ibp = (size_t)b * TLEN + (TLEN - 2);
        const int mb0 = (TLEN - 1) & 1;   // = 1
        const int pb0 = (TLEN - 2) & 1;   // = 0
        if (tid < 8)  alB[mb0 * 8  + tid] = g_alpha[ibl * 8  + tid];
        if (tid < 32) suB[mb0 * 32 + tid] = g_u    [ibl * 32 + tid];
        if (tid < 32) fmS[pb0 * 32 + tid] = out[ibp * 2112 + tid];
        *(float4*)(fcS + pb0 * (32 * LD) + i8 * LD + j8) =
            *(const float4*)(out + ibp * 2112 + 32 + i8 * 32 + j8);
    }
    __syncthreads();

    #pragma unroll 1
    for (int t = TLEN - 2; t >= 0; --t) {
        const size_t ib = (size_t)b * TLEN + t;
        const size_t ob = ib * 2112;
        const int pb = t & 1;          // fm/fc parity for this step
        const int mb = (t + 1) & 1;    // alpha/u parity for this step
        const bool hasprev = (t > 0);
        float* fcSp = fcS + pb * (32 * LD);
        float* fmSp = fmS + pb * 32;

        // prefetch for next (t-1) iteration
        float pfa = 0.f, pfu = 0.f, pfm = 0.f;
        float4 pfc = make_float4(0.f,0.f,0.f,0.f);
        if (tid < 8)  pfa = g_alpha[ib * 8  + tid];
        if (tid < 32) pfu = g_u    [ib * 32 + tid];
        if (hasprev) {
            const size_t obp = (ib - 1) * 2112;
            if (tid < 32) pfm = out[obp + tid];
            pfc = *(const float4*)(out + obp + 32 + i8 * 32 + j8);
        }

        // ---- P0: mixtures A, A^T, B(tmpM) for step t+1 ----
        {
            const float* al = alB + mb * 8;
            float4 aa = make_float4(0.f,0.f,0.f,0.f);
            float4 bb = make_float4(0.f,0.f,0.f,0.f);
            #pragma unroll
            for (int k = 0; k < 8; ++k) {
                const float w = al[k];
                float4 m = *(const float4*)(sAm + k * 1024 + i8 * 32 + j8);
                FMA4(aa, w, m);
                m = *(const float4*)(sBm + k * 1024 + i8 * 32 + j8);
                FMA4(bb, w, m);
            }
            *(float4*)(pA + i8 * LD + j8) = aa;
            pAtr[(j8 + 0) * LD + i8] = aa.x;
            pAtr[(j8 + 1) * LD + i8] = aa.y;
            pAtr[(j8 + 2) * LD + i8] = aa.z;
            pAtr[(j8 + 3) * LD + i8] = aa.w;
            *(float4*)(tmpM + i8 * LD + j8) = bb;
        }
        __syncthreads();

        // ---- P1: dz = zs - (A fm + B u) ; N = A fc -> aug0 right half ----
        if (tid < 32) {
            const float* su = suB + mb * 32;
            float s = 0.f;
            #pragma unroll 8
            for (int k = 0; k < 32; ++k) s = fmaf(tmpM[tid * LD + k], su[k], s);
            #pragma unroll 8
            for (int k = 0; k < 32; ++k) s = fmaf(pA[tid * LD + k], fmSp[k], s);
            dz[tid] = zm[tid] - s;
        }
        {
            float4 acc = make_float4(0.f,0.f,0.f,0.f);
            #pragma unroll 8
            for (int k = 0; k < 32; ++k) {
                float a = pA[i8 * LD + k];
                float4 vv = *(const float4*)(fcSp + k * LD + j8);
                FMA4(acc, a, vv);
            }
            *(float4*)(aug0 + i8 * LDA + 32 + j8) = acc;
        }
        __syncthreads();

        // ---- P2: P_pred = N A^T + Q -> pPp and aug0 left half; store prefetch ----
        {
            float4 acc = make_float4(0.f,0.f,0.f,0.f);
            #pragma unroll 8
            for (int k = 0; k < 32; ++k) {
                float a = aug0[i8 * LDA + 32 + k];
                float4 vv = *(const float4*)(pAtr + k * LD + j8);
                FMA4(acc, a, vv);
            }
            int d = i8 - j8;
            if (d >= 0 && d < 4) ((float*)&acc)[d] += qd[i8];
            *(float4*)(pPp + i8 * LD + j8) = acc;
            *(float4*)(aug0 + i8 * LDA + j8) = acc;
        }
        if (tid < 8)  alB[pb * 8  + tid] = pfa;
        if (tid < 32) suB[pb * 32 + tid] = pfu;
        if (hasprev) {
            if (tid < 32) fmS[mb * 32 + tid] = pfm;
            *(float4*)(fcS + mb * (32 * LD) + i8 * LD + j8) = pfc;
        }
        __syncthreads();

        // ---- GJ: 32 pivots, 2 per phase, double-buffered (16 barriers) ----
        {
            float* Asrc = aug0; float* Adst = aug1;
            #pragma unroll 1
            for (int pp = 0; pp < 16; ++pp) {
                const int p = pp << 1, q = p | 1;
                float Mip = Asrc[g8i * LDA + p], Miq = Asrc[g8i * LDA + q];
                float Mpp = Asrc[p * LDA + p],  Mpq = Asrc[p * LDA + q];
                float Mqp = Asrc[q * LDA + p],  Mqq = Asrc[q * LDA + q];
                float inv1 = __fdividef(1.f, Mpp);
                float r1q  = Mpq * inv1;
                float inv2 = __fdividef(1.f, fmaf(-Mqp, r1q, Mqq));
                float E1iq = (g8i == p) ? r1q : fmaf(-Mip, r1q, Miq);
                #pragma unroll
                for (int c = 0; c < 8; ++c) {
                    int j = g8j + (c << 3);
                    float Mpj = Asrc[p * LDA + j];
                    float Mqj = Asrc[q * LDA + j];
                    float Mij = Asrc[g8i * LDA + j];
                    float r1j  = Mpj * inv1;
                    float E1ij = (g8i == p) ? r1j : fmaf(-Mip, r1j, Mij);
                    float r2j  = fmaf(-Mqp, r1j, Mqj) * inv2;
                    Adst[g8i * LDA + j] = (g8i == q) ? r2j : fmaf(-E1iq, r2j, E1ij);
                }
                float* tsw = Asrc; Asrc = Adst; Adst = tsw;
                __syncthreads();
            }
        }
        // result (Y = Ppred^-1 N = J^T in cols 32..63) in aug0

        // ---- P19: zs = fm + Y^T dz (write sm) ; D = Ps - Ppred -> tmpM ----
        if (tid < 32) {
            float s = 0.f;
            #pragma unroll 8
            for (int r = 0; r < 32; ++r) s = fmaf(aug0[r * LDA + 32 + tid], dz[r], s);
            float nm = fmSp[tid] + s;
            zm[tid] = nm;
            out[ob + 1056 + tid] = nm;
        }
        {
            float4 a  = *(const float4*)(zc  + i8 * LD + j8);
            float4 p4 = *(const float4*)(pPp + i8 * LD + j8);
            a.x -= p4.x; a.y -= p4.y; a.z -= p4.z; a.w -= p4.w;
            *(float4*)(tmpM + i8 * LD + j8) = a;
        }
        __syncthreads();

        // ---- P20: W = D Y -> pPp ----
        {
            float4 acc = make_float4(0.f,0.f,0.f,0.f);
            #pragma unroll 8
            for (int k = 0; k < 32; ++k) {
                float dv = tmpM[i8 * LD + k];
                float4 vv = *(const float4*)(aug0 + k * LDA + 32 + j8);
                FMA4(acc, dv, vv);
            }
            *(float4*)(pPp + i8 * LD + j8) = acc;
        }
        __syncthreads();

        // ---- P21: Ps = fc + Y^T W -> zc, write sc ----
        {
            float4 acc = *(const float4*)(fcSp + i8 * LD + j8);
            #pragma unroll 8
            for (int k = 0; k < 32; ++k) {
                float yv = aug0[k * LDA + 32 + i8];
                float4 wv = *(const float4*)(pPp + k * LD + j8);
                FMA4(acc, yv, wv);
            }
            *(float4*)(zc + i8 * LD + j8) = acc;
            *(float4*)(out + ob + 1088 + i8 * 32 + j8) = acc;
        }
        // no trailing barrier: next P0 writes only pA/pAtr/tmpM (tmpM last read
        // in P20, ordered by P20-end barrier); aug0 rewritten only after next
        // P0-end barrier.
    }
}

extern "C" void kernel_launch(void* const* d_in, const int* in_sizes, int n_in,
                              void* d_out, int out_size) {
    const float* g_a    = (const float*)d_in[0];
    const float* g_alpha= (const float*)d_in[1];
    const float* g_u    = (const float*)d_in[2];
    const float* g_A    = (const float*)d_in[3];
    const float* g_B    = (const float*)d_in[4];
    const float* g_C    = (const float*)d_in[5];
    const float* g_lQ   = (const float*)d_in[6];
    const float* g_lR   = (const float*)d_in[7];
    const float* g_z0m  = (const float*)d_in[8];
    const float* g_z0lv = (const float*)d_in[9];
    float* out = (float*)d_out;
    int B = in_sizes[0] / (TLEN * 16);
    size_t smem = SMEM_FLOATS * sizeof(float);
    cudaFuncSetAttribute(lgssm_kernel, cudaFuncAttributeMaxDynamicSharedMemorySize, (int)smem);
    lgssm_kernel<<<B, NT, smem>>>(g_a, g_alpha, g_u, g_A, g_B, g_C,
                                  g_lQ, g_lR, g_z0m, g_z0lv, out);
}

// round 4
// speedup vs baseline: 1.9555x; 1.0266x over previous
#include <cuda_runtime.h>

#define NT     512
#define TLEN   512
#define LD     36     // padded leading dim, 32-col matrices
#define LDA    68     // augmented GJ matrix leading dim
#define LDCT   20     // C-transpose leading dim

// ---- shared memory layout (float offsets) ----
#define O_SAM  0       // 8*32*32 A components
#define O_SBM  8192    // 8*32*32 B components
#define O_SCM  16384   // 8*16*32 C components
#define O_A    20480   // 32xLD   A_t
#define O_ATR  21632   // 32xLD   A_t^T
#define O_CM   22784   // 16xLD   C_t
#define O_CTR  23360   // 32xLDCT C_t^T
#define O_ZC   24000   // 32xLD   covariance state
#define O_TMP  25152   // 32xLD   scratch (B mixture / D)
#define O_PP   26304   // 32xLD   scratch (A*zc / P_pred / W)
#define O_CPM  27456   // 16xLD   M = C*P
#define O_AUG0 28032   // 32xLDA  GJ buffer 0
#define O_AUG1 30208   // 32xLDA  GJ buffer 1
#define O_FCS  32384   // 2 x 32xLD  filtered cov (parity)
#define O_FMS  34688   // 2 x 32     filtered mean (parity)
#define O_ZM   34752   // 32
#define O_ZM2  34784   // 32
#define O_AL   34816   // 2 x 8
#define O_SU   34832   // 2 x 32
#define O_SA   34896   // 2 x 16
#define O_AP   34928   // 16
#define O_DZ   34944   // 32
#define O_QD   34976   // 32
#define O_RD   35008   // 16
#define SMEM_FLOATS 35024

// acc (float2) += Arow[k] * B[k][jj..jj+1], k = 0..31, A row cached as float4
#define MM2ROW(acc, rowA, matB, ldB, jj)                                      \
  { _Pragma("unroll")                                                         \
    for (int k0 = 0; k0 < 32; k0 += 4) {                                      \
      float4 a4 = *(const float4*)((rowA) + k0);                              \
      float2 v0 = *(const float2*)((matB) + (k0+0)*(ldB) + (jj));             \
      float2 v1 = *(const float2*)((matB) + (k0+1)*(ldB) + (jj));             \
      float2 v2 = *(const float2*)((matB) + (k0+2)*(ldB) + (jj));             \
      float2 v3 = *(const float2*)((matB) + (k0+3)*(ldB) + (jj));             \
      acc.x = fmaf(a4.x, v0.x, acc.x); acc.y = fmaf(a4.x, v0.y, acc.y);       \
      acc.x = fmaf(a4.y, v1.x, acc.x); acc.y = fmaf(a4.y, v1.y, acc.y);       \
      acc.x = fmaf(a4.z, v2.x, acc.x); acc.y = fmaf(a4.z, v2.y, acc.y);       \
      acc.x = fmaf(a4.w, v3.x, acc.x); acc.y = fmaf(a4.w, v3.y, acc.y);       \
    } }

#define FMA4L(s4, m4, v4)                                                     \
    s4.x = fmaf(m4.x, v4.x, s4.x); s4.y = fmaf(m4.y, v4.y, s4.y);             \
    s4.z = fmaf(m4.z, v4.z, s4.z); s4.w = fmaf(m4.w, v4.w, s4.w);

// two-pivot GJ update of one column j (pivots p, q = p+1)
#define GJ2COL(Adst, Asrc, gi, jj)                                            \
  { float Mpj = Asrc[p * LDA + (jj)];                                         \
    float Mqj = Asrc[q * LDA + (jj)];                                         \
    float Mij = Asrc[(gi) * LDA + (jj)];                                      \
    float r1j  = Mpj * inv1;                                                  \
    float E1ij = ((gi) == p) ? r1j : fmaf(-Mip, r1j, Mij);                    \
    float r2j  = fmaf(-Mqp, r1j, Mqj) * inv2;                                 \
    Adst[(gi) * LDA + (jj)] = ((gi) == q) ? r2j : fmaf(-E1iq, r2j, E1ij); }

__global__ __launch_bounds__(NT, 1)
void lgssm_kernel(const float* __restrict__ g_a,   const float* __restrict__ g_alpha,
                  const float* __restrict__ g_u,   const float* __restrict__ g_A,
                  const float* __restrict__ g_B,   const float* __restrict__ g_C,
                  const float* __restrict__ g_lQ,  const float* __restrict__ g_lR,
                  const float* __restrict__ g_z0m, const float* __restrict__ g_z0lv,
                  float* __restrict__ out)
{
    extern __shared__ float sh[];
    float* sAm  = sh + O_SAM;
    float* sBm  = sh + O_SBM;
    float* sCm  = sh + O_SCM;
    float* pA   = sh + O_A;
    float* pAtr = sh + O_ATR;
    float* pCm  = sh + O_CM;
    float* pCtr = sh + O_CTR;
    float* zc   = sh + O_ZC;
    float* tmpM = sh + O_TMP;
    float* pPp  = sh + O_PP;
    float* pCPm = sh + O_CPM;
    float* aug0 = sh + O_AUG0;
    float* aug1 = sh + O_AUG1;
    float* fcS  = sh + O_FCS;   // + parity*1152
    float* fmS  = sh + O_FMS;   // + parity*32
    float* zm   = sh + O_ZM;
    float* zm2  = sh + O_ZM2;
    float* alB  = sh + O_AL;    // + parity*8
    float* suB  = sh + O_SU;    // + parity*32
    float* saB  = sh + O_SA;    // + parity*16
    float* apred= sh + O_AP;
    float* dz   = sh + O_DZ;
    float* qd   = sh + O_QD;
    float* rd   = sh + O_RD;

    const int tid = threadIdx.x;
    const int b   = blockIdx.x;
    const int i16 = tid >> 4;          // 0..31 row
    const int j2  = (tid & 15) << 1;   // col base 0,2..30

    // ---- preload constants, noise diagonals, t=0 inputs, init state ----
    for (int idx = tid; idx < 8192; idx += NT) sAm[idx] = g_A[idx];
    for (int idx = tid; idx < 8192; idx += NT) sBm[idx] = g_B[idx];
    for (int idx = tid; idx < 4096; idx += NT) sCm[idx] = g_C[idx];
    if (tid < 32) qd[tid] = expf(g_lQ[tid]);
    if (tid < 16) rd[tid] = expf(g_lR[tid]);
    {
        const size_t ib0 = (size_t)b * TLEN;
        if (tid < 8)  alB[tid] = g_alpha[ib0 * 8  + tid];
        if (tid < 32) suB[tid] = g_u    [ib0 * 32 + tid];
        if (tid < 16) saB[tid] = g_a    [ib0 * 16 + tid];
        if (tid < 32) zm[tid] = g_z0m[tid];
        float2 v = make_float2(0.f, 0.f);
        if (i16 == j2)          v.x = expf(g_z0lv[i16]);
        else if (i16 == j2 + 1) v.y = expf(g_z0lv[i16]);
        *(float2*)(zc + i16 * LD + j2) = v;
    }
    __syncthreads();

    // =============== FORWARD FILTER ===============
    #pragma unroll 1
    for (int t = 0; t < TLEN; ++t) {
        const size_t ib = (size_t)b * TLEN + t;
        const int pb = t & 1, nb = pb ^ 1;
        const bool hasnext = (t + 1 < TLEN);

        // prefetch next step's inputs into registers (stored in P4)
        float pfa = 0.f, pfu = 0.f, pfo = 0.f;
        if (hasnext) {
            if (tid < 8)  pfa = g_alpha[(ib + 1) * 8  + tid];
            if (tid < 32) pfu = g_u    [(ib + 1) * 32 + tid];
            if (tid < 16) pfo = g_a    [(ib + 1) * 16 + tid];
        }

        // ---- P0: mixtures A, A^T, B(tmpM), C, C^T ----
        {
            const float* al = alB + pb * 8;
            float2 aa = make_float2(0.f, 0.f);
            float2 bb = make_float2(0.f, 0.f);
            #pragma unroll
            for (int k = 0; k < 8; ++k) {
                const float w = al[k];
                float2 m = *(const float2*)(sAm + k * 1024 + i16 * 32 + j2);
                aa.x = fmaf(w, m.x, aa.x); aa.y = fmaf(w, m.y, aa.y);
                m = *(const float2*)(sBm + k * 1024 + i16 * 32 + j2);
                bb.x = fmaf(w, m.x, bb.x); bb.y = fmaf(w, m.y, bb.y);
            }
            *(float2*)(pA + i16 * LD + j2) = aa;
            pAtr[(j2 + 0) * LD + i16] = aa.x;
            pAtr[(j2 + 1) * LD + i16] = aa.y;
            *(float2*)(tmpM + i16 * LD + j2) = bb;
            if (tid < 256) {   // i16 = 0..15 -> C rows
                float2 cc = make_float2(0.f, 0.f);
                #pragma unroll
                for (int k = 0; k < 8; ++k) {
                    const float w = al[k];
                    float2 m = *(const float2*)(sCm + k * 512 + i16 * 32 + j2);
                    cc.x = fmaf(w, m.x, cc.x); cc.y = fmaf(w, m.y, cc.y);
                }
                *(float2*)(pCm + i16 * LD + j2) = cc;
                pCtr[(j2 + 0) * LDCT + i16] = cc.x;
                pCtr[(j2 + 1) * LDCT + i16] = cc.y;
            }
        }
        __syncthreads();

        if (t > 0) {
            // ---- P1: zm2 = A zm + B u ; Pp = A zc ----
            if (tid < 32) {
                const float* su = suB + pb * 32;
                float4 s4 = make_float4(0.f, 0.f, 0.f, 0.f);
                #pragma unroll
                for (int k0 = 0; k0 < 32; k0 += 4) {
                    float4 m4 = *(const float4*)(tmpM + tid * LD + k0);
                    float4 v4 = *(const float4*)(su + k0);
                    FMA4L(s4, m4, v4);
                    m4 = *(const float4*)(pA + tid * LD + k0);
                    v4 = *(const float4*)(zm + k0);
                    FMA4L(s4, m4, v4);
                }
                zm2[tid] = (s4.x + s4.y) + (s4.z + s4.w);
            }
            {
                float2 acc = make_float2(0.f, 0.f);
                MM2ROW(acc, pA + i16 * LD, zc, LD, j2);
                *(float2*)(pPp + i16 * LD + j2) = acc;
            }
            __syncthreads();
            // ---- P2: zc = Pp A^T + Q ; zm = zm2 ----
            {
                float2 acc = make_float2(0.f, 0.f);
                MM2ROW(acc, pPp + i16 * LD, pAtr, LD, j2);
                if (i16 == j2)          acc.x += qd[i16];
                else if (i16 == j2 + 1) acc.y += qd[i16];
                *(float2*)(zc + i16 * LD + j2) = acc;
            }
            if (tid < 32) zm[tid] = zm2[tid];
            __syncthreads();
        }

        // ---- P3: M = C zc ; apred = C zm (idle tail threads) ----
        if (tid < 256) {
            float2 acc = make_float2(0.f, 0.f);
            MM2ROW(acc, pCm + i16 * LD, zc, LD, j2);
            *(float2*)(pCPm + i16 * LD + j2) = acc;
        } else if (tid >= 496) {
            int i = tid - 496;
            float4 s4 = make_float4(0.f, 0.f, 0.f, 0.f);
            #pragma unroll
            for (int k0 = 0; k0 < 32; k0 += 4) {
                float4 m4 = *(const float4*)(pCm + i * LD + k0);
                float4 v4 = *(const float4*)(zm + k0);
                FMA4L(s4, m4, v4);
            }
            apred[i] = (s4.x + s4.y) + (s4.z + s4.w);
        }
        __syncthreads();

        // ---- P4: aug0 = [S | M], dz = a - apred; store prefetched inputs ----
        if (tid < 128) {
            int i = tid >> 3, j0 = (tid & 7) << 1;
            float2 acc = make_float2(0.f, 0.f);
            MM2ROW(acc, pCPm + i * LD, pCtr, LDCT, j0);
            if (i == j0)          acc.x += rd[i];
            else if (i == j0 + 1) acc.y += rd[i];
            *(float2*)(aug0 + i * LDA + j0) = acc;
        } else if (tid < 144) {
            int j = tid - 128;
            dz[j] = saB[pb * 16 + j] - apred[j];
        } else if (tid >= 256) {
            int i = i16 - 16;  // 0..15
            *(float2*)(aug0 + i * LDA + 16 + j2) = *(const float2*)(pCPm + i * LD + j2);
        }
        if (hasnext) {
            if (tid < 8)  alB[nb * 8  + tid] = pfa;
            if (tid < 32) suB[nb * 32 + tid] = pfu;
            if (tid < 16) saB[nb * 16 + tid] = pfo;
        }
        __syncthreads();

        // ---- GJ: 16 pivots, 2 per phase, double-buffered (8 barriers) ----
        {
            const int gi = tid >> 5;       // 0..15
            const int gj = tid & 31;       // col 0..31 (+32 if gj<16)
            float* Asrc = aug0; float* Adst = aug1;
            #pragma unroll 1
            for (int pp = 0; pp < 8; ++pp) {
                const int p = pp << 1, q = p | 1;
                float Mip = Asrc[gi * LDA + p], Miq = Asrc[gi * LDA + q];
                float Mpp = Asrc[p * LDA + p],  Mpq = Asrc[p * LDA + q];
                float Mqp = Asrc[q * LDA + p],  Mqq = Asrc[q * LDA + q];
                float inv1 = __fdividef(1.f, Mpp);
                float r1q  = Mpq * inv1;
                float inv2 = __fdividef(1.f, fmaf(-Mqp, r1q, Mqq));
                float E1iq = (gi == p) ? r1q : fmaf(-Mip, r1q, Miq);
                GJ2COL(Adst, Asrc, gi, gj);
                if (gj < 16) GJ2COL(Adst, Asrc, gi, gj + 32);
                float* tsw = Asrc; Asrc = Adst; Adst = tsw;
                __syncthreads();
            }
        }
        // Kg^T in aug0 cols 16..47

        // ---- P13: measurement update + filtered output ----
        {
            const size_t ob = ib * 2112;
            // zm += Kg^T^T dz via width-16 shfl reduction (row = i16)
            {
                int lane16 = tid & 15;
                float v = aug0[lane16 * LDA + 16 + i16] * dz[lane16];
                #pragma unroll
                for (int off = 8; off; off >>= 1)
                    v += __shfl_xor_sync(0xffffffffu, v, off, 16);
                if (lane16 == 0) {
                    float nm = zm[i16] + v;
                    zm[i16] = nm;
                    out[ob + i16] = nm;
                    if (t == TLEN - 1) out[ob + 1056 + i16] = nm;
                }
            }
            float2 acc = *(const float2*)(zc + i16 * LD + j2);
            #pragma unroll
            for (int r = 0; r < 16; ++r) {
                float kv = aug0[r * LDA + 16 + i16];
                float2 mv = *(const float2*)(pCPm + r * LD + j2);
                acc.x = fmaf(-kv, mv.x, acc.x);
                acc.y = fmaf(-kv, mv.y, acc.y);
            }
            *(float2*)(zc + i16 * LD + j2) = acc;
            *(float2*)(out + ob + 32 + i16 * 32 + j2) = acc;
            if (t == TLEN - 1) *(float2*)(out + ob + 1088 + i16 * 32 + j2) = acc;
        }
        // no trailing barrier: next P0 touches disjoint smem
    }

    // =============== BACKWARD RTS SMOOTHER ===============
    __syncthreads();
    {   // preload buffers for first backward iteration (t = TLEN-2)
        const size_t ibl = (size_t)b * TLEN + (TLEN - 1);
        const size_t ibp = (size_t)b * TLEN + (TLEN - 2);
        const int mb0 = (TLEN - 1) & 1;   // 1
        const int pb0 = (TLEN - 2) & 1;   // 0
        if (tid < 8)  alB[mb0 * 8  + tid] = g_alpha[ibl * 8  + tid];
        if (tid < 32) suB[mb0 * 32 + tid] = g_u    [ibl * 32 + tid];
        if (tid < 32) fmS[pb0 * 32 + tid] = out[ibp * 2112 + tid];
        *(float2*)(fcS + pb0 * (32 * LD) + i16 * LD + j2) =
            *(const float2*)(out + ibp * 2112 + 32 + i16 * 32 + j2);
    }
    __syncthreads();

    #pragma unroll 1
    for (int t = TLEN - 2; t >= 0; --t) {
        const size_t ib = (size_t)b * TLEN + t;
        const size_t ob = ib * 2112;
        const int pb = t & 1;          // fm/fc parity for this step
        const int mb = (t + 1) & 1;    // alpha/u parity for this step
        const bool hasprev = (t > 0);
        float* fcSp = fcS + pb * (32 * LD);
        float* fmSp = fmS + pb * 32;

        // prefetch for next (t-1) iteration
        float pfa = 0.f, pfu = 0.f, pfm = 0.f;
        float2 pfc = make_float2(0.f, 0.f);
        if (tid < 8)  pfa = g_alpha[ib * 8  + tid];
        if (tid < 32) pfu = g_u    [ib * 32 + tid];
        if (hasprev) {
            const size_t obp = (ib - 1) * 2112;
            if (tid < 32) pfm = out[obp + tid];
            pfc = *(const float2*)(out + obp + 32 + i16 * 32 + j2);
        }

        // ---- P0: mixtures A, A^T, B(tmpM) for step t+1 ----
        {
            const float* al = alB + mb * 8;
            float2 aa = make_float2(0.f, 0.f);
            float2 bb = make_float2(0.f, 0.f);
            #pragma unroll
            for (int k = 0; k < 8; ++k) {
                const float w = al[k];
                float2 m = *(const float2*)(sAm + k * 1024 + i16 * 32 + j2);
                aa.x = fmaf(w, m.x, aa.x); aa.y = fmaf(w, m.y, aa.y);
                m = *(const float2*)(sBm + k * 1024 + i16 * 32 + j2);
                bb.x = fmaf(w, m.x, bb.x); bb.y = fmaf(w, m.y, bb.y);
            }
            *(float2*)(pA + i16 * LD + j2) = aa;
            pAtr[(j2 + 0) * LD + i16] = aa.x;
            pAtr[(j2 + 1) * LD + i16] = aa.y;
            *(float2*)(tmpM + i16 * LD + j2) = bb;
        }
        __syncthreads();

        // ---- P1: dz = zs - (A fm + B u) ; N = A fc -> aug0 cols 32..63 ----
        if (tid < 32) {
            const float* su = suB + mb * 32;
            float4 s4 = make_float4(0.f, 0.f, 0.f, 0.f);
            #pragma unroll
            for (int k0 = 0; k0 < 32; k0 += 4) {
                float4 m4 = *(const float4*)(tmpM + tid * LD + k0);
                float4 v4 = *(const float4*)(su + k0);
                FMA4L(s4, m4, v4);
                m4 = *(const float4*)(pA + tid * LD + k0);
                v4 = *(const float4*)(fmSp + k0);
                FMA4L(s4, m4, v4);
            }
            dz[tid] = zm[tid] - ((s4.x + s4.y) + (s4.z + s4.w));
        }
        {
            float2 acc = make_float2(0.f, 0.f);
            MM2ROW(acc, pA + i16 * LD, fcSp, LD, j2);
            *(float2*)(aug0 + i16 * LDA + 32 + j2) = acc;
        }
        __syncthreads();

        // ---- P2: P_pred = N A^T + Q -> pPp and aug0 left half; store prefetch ----
        {
            float2 acc = make_float2(0.f, 0.f);
            MM2ROW(acc, aug0 + i16 * LDA + 32, pAtr, LD, j2);
            if (i16 == j2)          acc.x += qd[i16];
            else if (i16 == j2 + 1) acc.y += qd[i16];
            *(float2*)(pPp + i16 * LD + j2) = acc;
            *(float2*)(aug0 + i16 * LDA + j2) = acc;
        }
        if (tid < 8)  alB[pb * 8  + tid] = pfa;
        if (tid < 32) suB[pb * 32 + tid] = pfu;
        if (hasprev) {
            if (tid < 32) fmS[mb * 32 + tid] = pfm;
            *(float2*)(fcS + mb * (32 * LD) + i16 * LD + j2) = pfc;
        }
        __syncthreads();

        // ---- GJ: 32 pivots, 2 per phase, double-buffered (16 barriers) ----
        {
            const int gi = tid >> 4;       // 0..31
            const int gj = tid & 15;       // cols gj, +16, +32, +48
            float* Asrc = aug0; float* Adst = aug1;
            #pragma unroll 1
            for (int pp = 0; pp < 16; ++pp) {
                const int p = pp << 1, q = p | 1;
                float Mip = Asrc[gi * LDA + p], Miq = Asrc[gi * LDA + q];
                float Mpp = Asrc[p * LDA + p],  Mpq = Asrc[p * LDA + q];
                float Mqp = Asrc[q * LDA + p],  Mqq = Asrc[q * LDA + q];
                float inv1 = __fdividef(1.f, Mpp);
                float r1q  = Mpq * inv1;
                float inv2 = __fdividef(1.f, fmaf(-Mqp, r1q, Mqq));
                float E1iq = (gi == p) ? r1q : fmaf(-Mip, r1q, Miq);
                GJ2COL(Adst, Asrc, gi, gj);
                GJ2COL(Adst, Asrc, gi, gj + 16);
                GJ2COL(Adst, Asrc, gi, gj + 32);
                GJ2COL(Adst, Asrc, gi, gj + 48);
                float* tsw = Asrc; Asrc = Adst; Adst = tsw;
                __syncthreads();
            }
        }
        // Y = Ppred^-1 N = J^T in aug0 cols 32..63

        // ---- P19: zs = fm + Y^T dz (shfl) ; D = Ps - Ppred -> tmpM ----
        {
            int lane = tid & 31;
            int o0 = (tid >> 5) << 1;   // 0,2,...,30 — each warp 2 outputs
            float v0 = aug0[lane * LDA + 32 + o0]     * dz[lane];
            float v1 = aug0[lane * LDA + 32 + o0 + 1] * dz[lane];
            #pragma unroll
            for (int off = 16; off; off >>= 1) {
                v0 += __shfl_xor_sync(0xffffffffu, v0, off);
                v1 += __shfl_xor_sync(0xffffffffu, v1, off);
            }
            if (lane == 0) {
                float nm0 = fmSp[o0] + v0;
                float nm1 = fmSp[o0 + 1] + v1;
                zm[o0] = nm0; zm[o0 + 1] = nm1;
                out[ob + 1056 + o0] = nm0;
                out[ob + 1056 + o0 + 1] = nm1;
            }
            float2 a  = *(const float2*)(zc  + i16 * LD + j2);
            float2 p2 = *(const float2*)(pPp + i16 * LD + j2);
            a.x -= p2.x; a.y -= p2.y;
            *(float2*)(tmpM + i16 * LD + j2) = a;
        }
        __syncthreads();

        // ---- P20: W = D Y -> pPp ----
        {
            float2 acc = make_float2(0.f, 0.f);
            MM2ROW(acc, tmpM + i16 * LD, aug0 + 32, LDA, j2);
            *(float2*)(pPp + i16 * LD + j2) = acc;
        }
        __syncthreads();

        // ---- P21: Ps = fc + Y^T W -> zc, write sc ----
        {
            float2 acc = *(const float2*)(fcSp + i16 * LD + j2);
            #pragma unroll
            for (int k = 0; k < 32; ++k) {
                float yv = aug0[k * LDA + 32 + i16];
                float2 wv = *(const float2*)(pPp + k * LD + j2);
                acc.x = fmaf(yv, wv.x, acc.x);
                acc.y = fmaf(yv, wv.y, acc.y);
            }
            *(float2*)(zc + i16 * LD + j2) = acc;
            *(float2*)(out + ob + 1088 + i16 * 32 + j2) = acc;
        }
        // no trailing barrier: next P0 writes pA/pAtr/tmpM; P21 reads none of them
    }
}

extern "C" void kernel_launch(void* const* d_in, const int* in_sizes, int n_in,
                              void* d_out, int out_size) {
    const float* g_a    = (const float*)d_in[0];
    const float* g_alpha= (const float*)d_in[1];
    const float* g_u    = (const float*)d_in[2];
    const float* g_A    = (const float*)d_in[3];
    const float* g_B    = (const float*)d_in[4];
    const float* g_C    = (const float*)d_in[5];
    const float* g_lQ   = (const float*)d_in[6];
    const float* g_lR   = (const float*)d_in[7];
    const float* g_z0m  = (const float*)d_in[8];
    const float* g_z0lv = (const float*)d_in[9];
    float* out = (float*)d_out;
    int B = in_sizes[0] / (TLEN * 16);
    size_t smem = SMEM_FLOATS * sizeof(float);
    cudaFuncSetAttribute(lgssm_kernel, cudaFuncAttributeMaxDynamicSharedMemorySize, (int)smem);
    lgssm_kernel<<<B, NT, smem>>>(g_a, g_alpha, g_u, g_A, g_B, g_C,
                                  g_lQ, g_lR, g_z0m, g_z0lv, out);
}

// round 5
// speedup vs baseline: 2.1021x; 1.0750x over previous
#include <cuda_runtime.h>

#define NT     512
#define TLEN   512
#define LD     36     // padded leading dim, 32-col matrices
#define LDA    68     // augmented GJ matrix leading dim
#define LDCT   20     // C-transpose leading dim

// ---- shared memory layout (float offsets) ----
#define O_SAM  0       // 8*32*32 A components
#define O_SBM  8192    // 8*32*32 B components
#define O_SCM  16384   // 8*16*32 C components
#define O_A    20480   // 32xLD   A_t
#define O_ATR  21632   // 32xLD   A_t^T
#define O_CM   22784   // 16xLD   C_t
#define O_CTR  23360   // 32xLDCT C_t^T
#define O_ZC   24000   // 32xLD   covariance state
#define O_TMP  25152   // 32xLD   scratch (B mixture / D)
#define O_PP   26304   // 32xLD   scratch (P_pred / W)
#define O_CPM  27456   // 16xLD   M = C*P
#define O_AUG0 28032   // 32xLDA  GJ buffer 0
#define O_AUG1 30208   // 32xLDA  GJ buffer 1
#define O_FCS  32384   // 2 x 32xLD  filtered cov (parity)
#define O_FMS  34688   // 2 x 32     filtered mean (parity)
#define O_ZM   34752   // 32
#define O_ZM2  34784   // 32
#define O_AL   34816   // 2 x 8
#define O_SU   34832   // 2 x 32
#define O_SA   34896   // 2 x 16
#define O_AP   34928   // 16
#define O_DZ   34944   // 32
#define O_QD   34976   // 32
#define O_RD   35008   // 16
#define SMEM_FLOATS 35024

#define FMA4S(acc, s, b)                                                      \
    acc.x = fmaf((s), (b).x, acc.x); acc.y = fmaf((s), (b).y, acc.y);         \
    acc.z = fmaf((s), (b).z, acc.z); acc.w = fmaf((s), (b).w, acc.w);

#define FMA4L(s4, m4, v4)                                                     \
    s4.x = fmaf(m4.x, v4.x, s4.x); s4.y = fmaf(m4.y, v4.y, s4.y);             \
    s4.z = fmaf(m4.z, v4.z, s4.z); s4.w = fmaf(m4.w, v4.w, s4.w);

// C[i][j..j+3] = rowA[0..31] . matB[0..31][j..j+3], dual accumulators
__device__ __forceinline__ float4 mm4(const float* __restrict__ rowA,
                                      const float* __restrict__ matB,
                                      const int ldB, const int jj) {
    float4 a0 = make_float4(0.f,0.f,0.f,0.f);
    float4 a1 = make_float4(0.f,0.f,0.f,0.f);
    #pragma unroll
    for (int k0 = 0; k0 < 32; k0 += 8) {
        float4 x = *(const float4*)(rowA + k0);
        float4 y = *(const float4*)(rowA + k0 + 4);
        const float* Bp = matB + k0 * ldB + jj;
        float4 b;
        b = *(const float4*)(Bp);           FMA4S(a0, x.x, b);
        b = *(const float4*)(Bp + ldB);     FMA4S(a1, x.y, b);
        b = *(const float4*)(Bp + 2*ldB);   FMA4S(a0, x.z, b);
        b = *(const float4*)(Bp + 3*ldB);   FMA4S(a1, x.w, b);
        b = *(const float4*)(Bp + 4*ldB);   FMA4S(a0, y.x, b);
        b = *(const float4*)(Bp + 5*ldB);   FMA4S(a1, y.y, b);
        b = *(const float4*)(Bp + 6*ldB);   FMA4S(a0, y.z, b);
        b = *(const float4*)(Bp + 7*ldB);   FMA4S(a1, y.w, b);
    }
    return make_float4(a0.x + a1.x, a0.y + a1.y, a0.z + a1.z, a0.w + a1.w);
}

// ---- 4-pivot Gauss-Jordan: per-phase preamble (pivot block factorization) ----
#define GJ4PRE(Asrc, gi, p0v)                                                 \
    const int p0 = (p0v), p1 = p0 + 1, p2v = p0 + 2, p3v = p0 + 3;            \
    float P00=Asrc[p0*LDA+p0],  P01=Asrc[p0*LDA+p1],                          \
          P02=Asrc[p0*LDA+p2v], P03=Asrc[p0*LDA+p3v];                         \
    float P10=Asrc[p1*LDA+p0],  P11=Asrc[p1*LDA+p1],                          \
          P12=Asrc[p1*LDA+p2v], P13=Asrc[p1*LDA+p3v];                         \
    float P20=Asrc[p2v*LDA+p0], P21=Asrc[p2v*LDA+p1],                         \
          P22=Asrc[p2v*LDA+p2v],P23=Asrc[p2v*LDA+p3v];                        \
    float P30=Asrc[p3v*LDA+p0], P31=Asrc[p3v*LDA+p1],                         \
          P32=Asrc[p3v*LDA+p2v],P33=Asrc[p3v*LDA+p3v];                        \
    float inv0 = __fdividef(1.f, P00);                                        \
    float u01 = P01*inv0, u02 = P02*inv0, u03 = P03*inv0;                     \
    float a11 = fmaf(-P10,u01,P11); float inv1 = __fdividef(1.f, a11);        \
    float a12 = fmaf(-P10,u02,P12), a13 = fmaf(-P10,u03,P13);                 \
    float v12 = a12*inv1, v13 = a13*inv1;                                     \
    float a21 = fmaf(-P20,u01,P21);                                           \
    float a22 = fmaf(-a21,v12,fmaf(-P20,u02,P22));                            \
    float inv2 = __fdividef(1.f, a22);                                        \
    float a23 = fmaf(-a21,v13,fmaf(-P20,u03,P23)); float w23 = a23*inv2;      \
    float a31 = fmaf(-P30,u01,P31);                                           \
    float a32 = fmaf(-a31,v12,fmaf(-P30,u02,P32));                            \
    float a33 = fmaf(-a32,w23,fmaf(-a31,v13,fmaf(-P30,u03,P33)));             \
    float inv3 = __fdividef(1.f, a33);                                        \
    float c0  = Asrc[gi*LDA+p0];                                              \
    float mi1 = Asrc[gi*LDA+p1], mi2 = Asrc[gi*LDA+p2v], mi3 = Asrc[gi*LDA+p3v];\
    float c1  = ((gi)==p0) ? u01 : fmaf(-c0,u01,mi1);                         \
    float c2t = ((gi)==p0) ? u02 : fmaf(-c0,u02,mi2);                         \
    float c2  = ((gi)==p1) ? v12 : fmaf(-c1,v12,c2t);                         \
    float c3t = ((gi)==p0) ? u03 : fmaf(-c0,u03,mi3);                         \
    float c3u = ((gi)==p1) ? v13 : fmaf(-c1,v13,c3t);                         \
    float c3  = ((gi)==p2v)? w23 : fmaf(-c2,w23,c3u);

// per-column 4-pivot update
#define GJ4COL(Adst, Asrc, gi, jj)                                            \
  { float m0 = Asrc[p0*LDA+(jj)],  m1 = Asrc[p1*LDA+(jj)];                    \
    float m2 = Asrc[p2v*LDA+(jj)], m3 = Asrc[p3v*LDA+(jj)];                   \
    float mi = Asrc[(gi)*LDA+(jj)];                                           \
    float r0 = m0*inv0;                                                       \
    float E0 = ((gi)==p0) ? r0 : fmaf(-c0,r0,mi);                             \
    float t1 = fmaf(-P10,r0,m1); float r1 = t1*inv1;                          \
    float E1 = ((gi)==p1) ? r1 : fmaf(-c1,r1,E0);                             \
    float t2 = fmaf(-a21,r1,fmaf(-P20,r0,m2)); float r2 = t2*inv2;            \
    float E2 = ((gi)==p2v)? r2 : fmaf(-c2,r2,E1);                             \
    float t3 = fmaf(-a32,r2,fmaf(-a31,r1,fmaf(-P30,r0,m3)));                  \
    float r3 = t3*inv3;                                                       \
    Adst[(gi)*LDA+(jj)] = ((gi)==p3v)? r3 : fmaf(-c3,r3,E2); }

__global__ __launch_bounds__(NT, 1)
void lgssm_kernel(const float* __restrict__ g_a,   const float* __restrict__ g_alpha,
                  const float* __restrict__ g_u,   const float* __restrict__ g_A,
                  const float* __restrict__ g_B,   const float* __restrict__ g_C,
                  const float* __restrict__ g_lQ,  const float* __restrict__ g_lR,
                  const float* __restrict__ g_z0m, const float* __restrict__ g_z0lv,
                  float* __restrict__ out)
{
    extern __shared__ float sh[];
    float* sAm  = sh + O_SAM;
    float* sBm  = sh + O_SBM;
    float* sCm  = sh + O_SCM;
    float* pA   = sh + O_A;
    float* pAtr = sh + O_ATR;
    float* pCm  = sh + O_CM;
    float* pCtr = sh + O_CTR;
    float* zc   = sh + O_ZC;
    float* tmpM = sh + O_TMP;
    float* pPp  = sh + O_PP;
    float* pCPm = sh + O_CPM;
    float* aug0 = sh + O_AUG0;
    float* aug1 = sh + O_AUG1;
    float* fcS  = sh + O_FCS;
    float* fmS  = sh + O_FMS;
    float* zm   = sh + O_ZM;
    float* zm2  = sh + O_ZM2;
    float* alB  = sh + O_AL;
    float* suB  = sh + O_SU;
    float* saB  = sh + O_SA;
    float* apred= sh + O_AP;
    float* dz   = sh + O_DZ;
    float* qd   = sh + O_QD;
    float* rd   = sh + O_RD;

    const int tid = threadIdx.x;
    const int b   = blockIdx.x;
    const int i16 = tid >> 4;          // 0..31 (float2 maps)
    const int j2  = (tid & 15) << 1;
    const int i4  = tid >> 3;          // 0..31 for tid<256 (float4 maps)
    const int j4  = (tid & 7) << 2;    // 0,4..28

    // ---- preload constants, noise diagonals, t=0 inputs, init state ----
    for (int idx = tid; idx < 8192; idx += NT) sAm[idx] = g_A[idx];
    for (int idx = tid; idx < 8192; idx += NT) sBm[idx] = g_B[idx];
    for (int idx = tid; idx < 4096; idx += NT) sCm[idx] = g_C[idx];
    if (tid < 32) qd[tid] = expf(g_lQ[tid]);
    if (tid < 16) rd[tid] = expf(g_lR[tid]);
    {
        const size_t ib0 = (size_t)b * TLEN;
        if (tid < 8)  alB[tid] = g_alpha[ib0 * 8  + tid];
        if (tid < 32) suB[tid] = g_u    [ib0 * 32 + tid];
        if (tid < 16) saB[tid] = g_a    [ib0 * 16 + tid];
        if (tid < 32) zm[tid] = g_z0m[tid];
        float2 v = make_float2(0.f, 0.f);
        if (i16 == j2)          v.x = expf(g_z0lv[i16]);
        else if (i16 == j2 + 1) v.y = expf(g_z0lv[i16]);
        *(float2*)(zc + i16 * LD + j2) = v;
    }
    __syncthreads();

    // =============== FORWARD FILTER ===============
    #pragma unroll 1
    for (int t = 0; t < TLEN; ++t) {
        const size_t ib = (size_t)b * TLEN + t;
        const int pb = t & 1, nb = pb ^ 1;
        const bool hasnext = (t + 1 < TLEN);

        float pfa = 0.f, pfu = 0.f, pfo = 0.f;
        if (hasnext) {
            if (tid < 8)  pfa = g_alpha[(ib + 1) * 8  + tid];
            if (tid < 32) pfu = g_u    [(ib + 1) * 32 + tid];
            if (tid < 16) pfo = g_a    [(ib + 1) * 16 + tid];
        }

        // ---- P0: mixtures A, A^T, B(tmpM), C, C^T ----
        {
            const float* al = alB + pb * 8;
            float2 aa = make_float2(0.f, 0.f);
            float2 bb = make_float2(0.f, 0.f);
            #pragma unroll
            for (int k = 0; k < 8; ++k) {
                const float w = al[k];
                float2 m = *(const float2*)(sAm + k * 1024 + i16 * 32 + j2);
                aa.x = fmaf(w, m.x, aa.x); aa.y = fmaf(w, m.y, aa.y);
                m = *(const float2*)(sBm + k * 1024 + i16 * 32 + j2);
                bb.x = fmaf(w, m.x, bb.x); bb.y = fmaf(w, m.y, bb.y);
            }
            *(float2*)(pA + i16 * LD + j2) = aa;
            pAtr[(j2 + 0) * LD + i16] = aa.x;
            pAtr[(j2 + 1) * LD + i16] = aa.y;
            *(float2*)(tmpM + i16 * LD + j2) = bb;
            if (tid < 256) {
                float2 cc = make_float2(0.f, 0.f);
                #pragma unroll
                for (int k = 0; k < 8; ++k) {
                    const float w = al[k];
                    float2 m = *(const float2*)(sCm + k * 512 + i16 * 32 + j2);
                    cc.x = fmaf(w, m.x, cc.x); cc.y = fmaf(w, m.y, cc.y);
                }
                *(float2*)(pCm + i16 * LD + j2) = cc;
                pCtr[(j2 + 0) * LDCT + i16] = cc.x;
                pCtr[(j2 + 1) * LDCT + i16] = cc.y;
            }
        }
        __syncthreads();

        if (t > 0) {
            // ---- P1: Pp = A zc (256 thr) ; zm2 = A zm + B u (32 thr) ----
            if (tid < 256) {
                float4 acc = mm4(pA + i4 * LD, zc, LD, j4);
                *(float4*)(pPp + i4 * LD + j4) = acc;
            } else if (tid >= 480) {
                const int i = tid - 480;
                const float* su = suB + pb * 32;
                float4 s4 = make_float4(0.f, 0.f, 0.f, 0.f);
                #pragma unroll
                for (int k0 = 0; k0 < 32; k0 += 4) {
                    float4 m4 = *(const float4*)(tmpM + i * LD + k0);
                    float4 v4 = *(const float4*)(su + k0);
                    FMA4L(s4, m4, v4);
                    m4 = *(const float4*)(pA + i * LD + k0);
                    v4 = *(const float4*)(zm + k0);
                    FMA4L(s4, m4, v4);
                }
                zm2[i] = (s4.x + s4.y) + (s4.z + s4.w);
            }
            __syncthreads();
            // ---- P2: zc = Pp A^T + Q ; zm = zm2 ----
            if (tid < 256) {
                float4 acc = mm4(pPp + i4 * LD, pAtr, LD, j4);
                int d = i4 - j4;
                if (d >= 0 && d < 4) ((float*)&acc)[d] += qd[i4];
                *(float4*)(zc + i4 * LD + j4) = acc;
            } else if (tid >= 480) {
                zm[tid - 480] = zm2[tid - 480];
            }
            __syncthreads();
        }

        // ---- P3: M = C zc (128 thr) ; apred = C zm (16 thr) ----
        if (tid < 128) {
            float4 acc = mm4(pCm + i4 * LD, zc, LD, j4);
            *(float4*)(pCPm + i4 * LD + j4) = acc;
        } else if (tid >= 496) {
            const int i = tid - 496;
            float4 s4 = make_float4(0.f, 0.f, 0.f, 0.f);
            #pragma unroll
            for (int k0 = 0; k0 < 32; k0 += 4) {
                float4 m4 = *(const float4*)(pCm + i * LD + k0);
                float4 v4 = *(const float4*)(zm + k0);
                FMA4L(s4, m4, v4);
            }
            apred[i] = (s4.x + s4.y) + (s4.z + s4.w);
        }
        __syncthreads();

        // ---- P4: aug0 = [S | M], dz = a - apred; store prefetched inputs ----
        if (tid < 64) {
            const int i = tid >> 2, j0 = (tid & 3) << 2;
            float4 acc = mm4(pCPm + i * LD, pCtr, LDCT, j0);
            int d = i - j0;
            if (d >= 0 && d < 4) ((float*)&acc)[d] += rd[i];
            *(float4*)(aug0 + i * LDA + j0) = acc;
        } else if (tid >= 128 && tid < 144) {
            const int j = tid - 128;
            dz[j] = saB[pb * 16 + j] - apred[j];
        } else if (tid >= 256 && tid < 384) {
            const int idx = tid - 256;
            const int i = idx >> 3, j0 = (idx & 7) << 2;
            *(float4*)(aug0 + i * LDA + 16 + j0) = *(const float4*)(pCPm + i * LD + j0);
        }
        if (hasnext) {
            if (tid < 8)  alB[nb * 8  + tid] = pfa;
            if (tid < 32) suB[nb * 32 + tid] = pfu;
            if (tid < 16) saB[nb * 16 + tid] = pfo;
        }
        __syncthreads();

        // ---- GJ: 16 pivots, 4 per phase (4 barriers) ----
        {
            const int gi = tid >> 5;       // 0..15
            const int gj = tid & 31;       // col gj; +32 if gj<16
            float* Asrc = aug0; float* Adst = aug1;
            #pragma unroll 1
            for (int pp = 0; pp < 4; ++pp) {
                GJ4PRE(Asrc, gi, pp << 2);
                GJ4COL(Adst, Asrc, gi, gj);
                if (gj < 16) GJ4COL(Adst, Asrc, gi, gj + 32);
                float* tsw = Asrc; Asrc = Adst; Adst = tsw;
                __syncthreads();
            }
        }
        // Kg^T in aug0 cols 16..47

        // ---- P13: measurement update + filtered output ----
        {
            const size_t ob = ib * 2112;
            {   // zm += Kg dz via width-16 shfl (all 512 threads, row = i16)
                int lane16 = tid & 15;
                float v = aug0[lane16 * LDA + 16 + i16] * dz[lane16];
                #pragma unroll
                for (int off = 8; off; off >>= 1)
                    v += __shfl_xor_sync(0xffffffffu, v, off, 16);
                if (lane16 == 0) {
                    float nm = zm[i16] + v;
                    zm[i16] = nm;
                    out[ob + i16] = nm;
                    if (t == TLEN - 1) out[ob + 1056 + i16] = nm;
                }
            }
            if (tid < 256) {
                float4 acc = *(const float4*)(zc + i4 * LD + j4);
                #pragma unroll
                for (int r = 0; r < 16; ++r) {
                    float kv = aug0[r * LDA + 16 + i4];
                    float4 mv = *(const float4*)(pCPm + r * LD + j4);
                    acc.x = fmaf(-kv, mv.x, acc.x);
                    acc.y = fmaf(-kv, mv.y, acc.y);
                    acc.z = fmaf(-kv, mv.z, acc.z);
                    acc.w = fmaf(-kv, mv.w, acc.w);
                }
                *(float4*)(zc + i4 * LD + j4) = acc;
                *(float4*)(out + ob + 32 + i4 * 32 + j4) = acc;
                if (t == TLEN - 1) *(float4*)(out + ob + 1088 + i4 * 32 + j4) = acc;
            }
        }
        // no trailing barrier: next P0 touches disjoint smem; P0-end barrier orders zm/zc
    }

    // =============== BACKWARD RTS SMOOTHER ===============
    __syncthreads();
    {   // preload buffers for first backward iteration (t = TLEN-2)
        const size_t ibl = (size_t)b * TLEN + (TLEN - 1);
        const size_t ibp = (size_t)b * TLEN + (TLEN - 2);
        const int mb0 = (TLEN - 1) & 1;   // 1
        const int pb0 = (TLEN - 2) & 1;   // 0
        if (tid < 8)  alB[mb0 * 8  + tid] = g_alpha[ibl * 8  + tid];
        if (tid < 32) suB[mb0 * 32 + tid] = g_u    [ibl * 32 + tid];
        if (tid < 32) fmS[pb0 * 32 + tid] = out[ibp * 2112 + tid];
        *(float2*)(fcS + pb0 * (32 * LD) + i16 * LD + j2) =
            *(const float2*)(out + ibp * 2112 + 32 + i16 * 32 + j2);
    }
    __syncthreads();

    #pragma unroll 1
    for (int t = TLEN - 2; t >= 0; --t) {
        const size_t ib = (size_t)b * TLEN + t;
        const size_t ob = ib * 2112;
        const int pb = t & 1;          // fm/fc parity
        const int mb = (t + 1) & 1;    // alpha/u parity
        const bool hasprev = (t > 0);
        float* fcSp = fcS + pb * (32 * LD);
        float* fmSp = fmS + pb * 32;

        float pfa = 0.f, pfu = 0.f, pfm = 0.f;
        float2 pfc = make_float2(0.f, 0.f);
        if (tid < 8)  pfa = g_alpha[ib * 8  + tid];
        if (tid < 32) pfu = g_u    [ib * 32 + tid];
        if (hasprev) {
            const size_t obp = (ib - 1) * 2112;
            if (tid < 32) pfm = out[obp + tid];
            pfc = *(const float2*)(out + obp + 32 + i16 * 32 + j2);
        }

        // ---- P0: mixtures A, A^T, B(tmpM) for step t+1 ----
        {
            const float* al = alB + mb * 8;
            float2 aa = make_float2(0.f, 0.f);
            float2 bb = make_float2(0.f, 0.f);
            #pragma unroll
            for (int k = 0; k < 8; ++k) {
                const float w = al[k];
                float2 m = *(const float2*)(sAm + k * 1024 + i16 * 32 + j2);
                aa.x = fmaf(w, m.x, aa.x); aa.y = fmaf(w, m.y, aa.y);
                m = *(const float2*)(sBm + k * 1024 + i16 * 32 + j2);
                bb.x = fmaf(w, m.x, bb.x); bb.y = fmaf(w, m.y, bb.y);
            }
            *(float2*)(pA + i16 * LD + j2) = aa;
            pAtr[(j2 + 0) * LD + i16] = aa.x;
            pAtr[(j2 + 1) * LD + i16] = aa.y;
            *(float2*)(tmpM + i16 * LD + j2) = bb;
        }
        __syncthreads();

        // ---- P1: N = A fc -> aug0 cols 32..63 (256 thr) ; dz (32 thr) ----
        if (tid < 256) {
            float4 acc = mm4(pA + i4 * LD, fcSp, LD, j4);
            *(float4*)(aug0 + i4 * LDA + 32 + j4) = acc;
        } else if (tid >= 480) {
            const int i = tid - 480;
            const float* su = suB + mb * 32;
            float4 s4 = make_float4(0.f, 0.f, 0.f, 0.f);
            #pragma unroll
            for (int k0 = 0; k0 < 32; k0 += 4) {
                float4 m4 = *(const float4*)(tmpM + i * LD + k0);
                float4 v4 = *(const float4*)(su + k0);
                FMA4L(s4, m4, v4);
                m4 = *(const float4*)(pA + i * LD + k0);
                v4 = *(const float4*)(fmSp + k0);
                FMA4L(s4, m4, v4);
            }
            dz[i] = zm[i] - ((s4.x + s4.y) + (s4.z + s4.w));
        }
        __syncthreads();

        // ---- P2: P_pred = N A^T + Q -> pPp and aug0 left; store prefetch ----
        if (tid < 256) {
            float4 acc = mm4(aug0 + i4 * LDA + 32, pAtr, LD, j4);
            int d = i4 - j4;
            if (d >= 0 && d < 4) ((float*)&acc)[d] += qd[i4];
            *(float4*)(pPp + i4 * LD + j4) = acc;
            *(float4*)(aug0 + i4 * LDA + j4) = acc;
        }
        if (tid < 8)  alB[pb * 8  + tid] = pfa;
        if (tid < 32) suB[pb * 32 + tid] = pfu;
        if (hasprev) {
            if (tid < 32) fmS[mb * 32 + tid] = pfm;
            *(float2*)(fcS + mb * (32 * LD) + i16 * LD + j2) = pfc;
        }
        __syncthreads();

        // ---- GJ: 32 pivots, 4 per phase (8 barriers) ----
        {
            const int gi = tid >> 4;       // 0..31
            const int gj = tid & 15;       // cols gj, +16, +32, +48
            float* Asrc = aug0; float* Adst = aug1;
            #pragma unroll 1
            for (int pp = 0; pp < 8; ++pp) {
                GJ4PRE(Asrc, gi, pp << 2);
                GJ4COL(Adst, Asrc, gi, gj);
                GJ4COL(Adst, Asrc, gi, gj + 16);
                GJ4COL(Adst, Asrc, gi, gj + 32);
                GJ4COL(Adst, Asrc, gi, gj + 48);
                float* tsw = Asrc; Asrc = Adst; Adst = tsw;
                __syncthreads();
            }
        }
        // Y = Ppred^-1 N = J^T in aug0 cols 32..63

        // ---- P19: zs = fm + Y^T dz (shfl) ; D = Ps - Ppred -> tmpM ----
        {
            int lane = tid & 31;
            int o0 = (tid >> 5) << 1;   // each warp 2 outputs
            float v0 = aug0[lane * LDA + 32 + o0]     * dz[lane];
            float v1 = aug0[lane * LDA + 32 + o0 + 1] * dz[lane];
            #pragma unroll
            for (int off = 16; off; off >>= 1) {
                v0 += __shfl_xor_sync(0xffffffffu, v0, off);
                v1 += __shfl_xor_sync(0xffffffffu, v1, off);
            }
            if (lane == 0) {
                float nm0 = fmSp[o0] + v0;
                float nm1 = fmSp[o0 + 1] + v1;
                zm[o0] = nm0; zm[o0 + 1] = nm1;
                out[ob + 1056 + o0] = nm0;
                out[ob + 1056 + o0 + 1] = nm1;
            }
            float2 a  = *(const float2*)(zc  + i16 * LD + j2);
            float2 p2 = *(const float2*)(pPp + i16 * LD + j2);
            a.x -= p2.x; a.y -= p2.y;
            *(float2*)(tmpM + i16 * LD + j2) = a;
        }
        __syncthreads();

        // ---- P20: W = D Y -> pPp (256 thr) ----
        if (tid < 256) {
            float4 acc = mm4(tmpM + i4 * LD, aug0 + 32, LDA, j4);
            *(float4*)(pPp + i4 * LD + j4) = acc;
        }
        __syncthreads();

        // ---- P21: Ps = fc + Y^T W -> zc, write sc (256 thr) ----
        if (tid < 256) {
            float4 acc = *(const float4*)(fcSp + i4 * LD + j4);
            #pragma unroll
            for (int k = 0; k < 32; ++k) {
                float yv = aug0[k * LDA + 32 + i4];
                float4 wv = *(const float4*)(pPp + k * LD + j4);
                FMA4S(acc, yv, wv);
            }
            *(float4*)(zc + i4 * LD + j4) = acc;
            *(float4*)(out + ob + 1088 + i4 * 32 + j4) = acc;
        }
        // no trailing barrier: next P0 writes pA/pAtr/tmpM, none read in P21
    }
}

extern "C" void kernel_launch(void* const* d_in, const int* in_sizes, int n_in,
                              void* d_out, int out_size) {
    const float* g_a    = (const float*)d_in[0];
    const float* g_alpha= (const float*)d_in[1];
    const float* g_u    = (const float*)d_in[2];
    const float* g_A    = (const float*)d_in[3];
    const float* g_B    = (const float*)d_in[4];
    const float* g_C    = (const float*)d_in[5];
    const float* g_lQ   = (const float*)d_in[6];
    const float* g_lR   = (const float*)d_in[7];
    const float* g_z0m  = (const float*)d_in[8];
    const float* g_z0lv = (const float*)d_in[9];
    float* out = (float*)d_out;
    int B = in_sizes[0] / (TLEN * 16);
    size_t smem = SMEM_FLOATS * sizeof(float);
    cudaFuncSetAttribute(lgssm_kernel, cudaFuncAttributeMaxDynamicSharedMemorySize, (int)smem);
    lgssm_kernel<<<B, NT, smem>>>(g_a, g_alpha, g_u, g_A, g_B, g_C,
                                  g_lQ, g_lR, g_z0m, g_z0lv, out);
}

// round 6
// speedup vs baseline: 2.1052x; 1.0015x over previous
#include <cuda_runtime.h>

#define NT     512
#define TLEN   512
#define LD     36     // padded leading dim, 32-col matrices
#define LDA    68     // augmented GJ matrix leading dim
#define LDCT   20     // C-transpose leading dim

// ---- shared memory layout (float offsets) ----
#define O_SAM  0       // 8*32*32 A components
#define O_SBM  8192    // 8*32*32 B components
#define O_SCM  16384   // 8*16*32 C components
#define O_A    20480   // 32xLD   A_t
#define O_ATR  21632   // 32xLD   A_t^T
#define O_CM   22784   // 16xLD   C_t
#define O_CTR  23360   // 32xLDCT C_t^T
#define O_ZC   24000   // 32xLD   covariance state
#define O_TMP  25152   // 32xLD   scratch (B mixture / D)
#define O_PP   26304   // 32xLD   scratch (P_pred / W)
#define O_CPM  27456   // 16xLD   M = C*P
#define O_AUG0 28032   // 32xLDA  GJ buffer 0
#define O_AUG1 30208   // 32xLDA  GJ buffer 1
#define O_FCS  32384   // 2 x 32xLD  filtered cov (parity)
#define O_FMS  34688   // 2 x 32     filtered mean (parity)
#define O_ZM   34752   // 32
#define O_ZM2  34784   // 32
#define O_AL   34816   // 2 x 8
#define O_SU   34832   // 2 x 32
#define O_SA   34896   // 2 x 16
#define O_AP   34928   // 16
#define O_DZ   34944   // 32
#define O_QD   34976   // 32
#define O_RD   35008   // 16
#define SMEM_FLOATS 35024

#define FMA4S(acc, s, b)                                                      \
    acc.x = fmaf((s), (b).x, acc.x); acc.y = fmaf((s), (b).y, acc.y);         \
    acc.z = fmaf((s), (b).z, acc.z); acc.w = fmaf((s), (b).w, acc.w);

#define FMA4L(s4, m4, v4)                                                     \
    s4.x = fmaf(m4.x, v4.x, s4.x); s4.y = fmaf(m4.y, v4.y, s4.y);             \
    s4.z = fmaf(m4.z, v4.z, s4.z); s4.w = fmaf(m4.w, v4.w, s4.w);

// C[i][j..j+3] = rowA[0..31] . matB[0..31][j..j+3], dual accumulators
__device__ __forceinline__ float4 mm4(const float* __restrict__ rowA,
                                      const float* __restrict__ matB,
                                      const int ldB, const int jj) {
    float4 a0 = make_float4(0.f,0.f,0.f,0.f);
    float4 a1 = make_float4(0.f,0.f,0.f,0.f);
    #pragma unroll
    for (int k0 = 0; k0 < 32; k0 += 8) {
        float4 x = *(const float4*)(rowA + k0);
        float4 y = *(const float4*)(rowA + k0 + 4);
        const float* Bp = matB + k0 * ldB + jj;
        float4 b;
        b = *(const float4*)(Bp);           FMA4S(a0, x.x, b);
        b = *(const float4*)(Bp + ldB);     FMA4S(a1, x.y, b);
        b = *(const float4*)(Bp + 2*ldB);   FMA4S(a0, x.z, b);
        b = *(const float4*)(Bp + 3*ldB);   FMA4S(a1, x.w, b);
        b = *(const float4*)(Bp + 4*ldB);   FMA4S(a0, y.x, b);
        b = *(const float4*)(Bp + 5*ldB);   FMA4S(a1, y.y, b);
        b = *(const float4*)(Bp + 6*ldB);   FMA4S(a0, y.z, b);
        b = *(const float4*)(Bp + 7*ldB);   FMA4S(a1, y.w, b);
    }
    return make_float4(a0.x + a1.x, a0.y + a1.y, a0.z + a1.z, a0.w + a1.w);
}

// ---- 4-pivot Gauss-Jordan: per-phase preamble (pivot block factorization) ----
#define GJ4PRE(Asrc, gi, p0v)                                                 \
    const int p0 = (p0v), p1 = p0 + 1, p2v = p0 + 2, p3v = p0 + 3;            \
    float P00=Asrc[p0*LDA+p0],  P01=Asrc[p0*LDA+p1],                          \
          P02=Asrc[p0*LDA+p2v], P03=Asrc[p0*LDA+p3v];                         \
    float P10=Asrc[p1*LDA+p0],  P11=Asrc[p1*LDA+p1],                          \
          P12=Asrc[p1*LDA+p2v], P13=Asrc[p1*LDA+p3v];                         \
    float P20=Asrc[p2v*LDA+p0], P21=Asrc[p2v*LDA+p1],                         \
          P22=Asrc[p2v*LDA+p2v],P23=Asrc[p2v*LDA+p3v];                        \
    float P30=Asrc[p3v*LDA+p0], P31=Asrc[p3v*LDA+p1],                         \
          P32=Asrc[p3v*LDA+p2v],P33=Asrc[p3v*LDA+p3v];                        \
    float inv0 = __fdividef(1.f, P00);                                        \
    float u01 = P01*inv0, u02 = P02*inv0, u03 = P03*inv0;                     \
    float a11 = fmaf(-P10,u01,P11); float inv1 = __fdividef(1.f, a11);        \
    float a12 = fmaf(-P10,u02,P12), a13 = fmaf(-P10,u03,P13);                 \
    float v12 = a12*inv1, v13 = a13*inv1;                                     \
    float a21 = fmaf(-P20,u01,P21);                                           \
    float a22 = fmaf(-a21,v12,fmaf(-P20,u02,P22));                            \
    float inv2 = __fdividef(1.f, a22);                                        \
    float a23 = fmaf(-a21,v13,fmaf(-P20,u03,P23)); float w23 = a23*inv2;      \
    float a31 = fmaf(-P30,u01,P31);                                           \
    float a32 = fmaf(-a31,v12,fmaf(-P30,u02,P32));                            \
    float a33 = fmaf(-a32,w23,fmaf(-a31,v13,fmaf(-P30,u03,P33)));             \
    float inv3 = __fdividef(1.f, a33);                                        \
    float c0  = Asrc[gi*LDA+p0];                                              \
    float mi1 = Asrc[gi*LDA+p1], mi2 = Asrc[gi*LDA+p2v], mi3 = Asrc[gi*LDA+p3v];\
    float c1  = ((gi)==p0) ? u01 : fmaf(-c0,u01,mi1);                         \
    float c2t = ((gi)==p0) ? u02 : fmaf(-c0,u02,mi2);                         \
    float c2  = ((gi)==p1) ? v12 : fmaf(-c1,v12,c2t);                         \
    float c3t = ((gi)==p0) ? u03 : fmaf(-c0,u03,mi3);                         \
    float c3u = ((gi)==p1) ? v13 : fmaf(-c1,v13,c3t);                         \
    float c3  = ((gi)==p2v)? w23 : fmaf(-c2,w23,c3u);

// per-column 4-pivot update
#define GJ4COL(Adst, Asrc, gi, jj)                                            \
  { float m0 = Asrc[p0*LDA+(jj)],  m1 = Asrc[p1*LDA+(jj)];                    \
    float m2 = Asrc[p2v*LDA+(jj)], m3 = Asrc[p3v*LDA+(jj)];                   \
    float mi = Asrc[(gi)*LDA+(jj)];                                           \
    float r0 = m0*inv0;                                                       \
    float E0 = ((gi)==p0) ? r0 : fmaf(-c0,r0,mi);                             \
    float t1 = fmaf(-P10,r0,m1); float r1 = t1*inv1;                          \
    float E1 = ((gi)==p1) ? r1 : fmaf(-c1,r1,E0);                             \
    float t2 = fmaf(-a21,r1,fmaf(-P20,r0,m2)); float r2 = t2*inv2;            \
    float E2 = ((gi)==p2v)? r2 : fmaf(-c2,r2,E1);                             \
    float t3 = fmaf(-a32,r2,fmaf(-a31,r1,fmaf(-P30,r0,m3)));                  \
    float r3 = t3*inv3;                                                       \
    Adst[(gi)*LDA+(jj)] = ((gi)==p3v)? r3 : fmaf(-c3,r3,E2); }

__global__ __launch_bounds__(NT, 1)
void lgssm_kernel(const float* __restrict__ g_a,   const float* __restrict__ g_alpha,
                  const float* __restrict__ g_u,   const float* __restrict__ g_A,
                  const float* __restrict__ g_B,   const float* __restrict__ g_C,
                  const float* __restrict__ g_lQ,  const float* __restrict__ g_lR,
                  const float* __restrict__ g_z0m, const float* __restrict__ g_z0lv,
                  float* __restrict__ out)
{
    extern __shared__ float sh[];
    float* sAm  = sh + O_SAM;
    float* sBm  = sh + O_SBM;
    float* sCm  = sh + O_SCM;
    float* pA   = sh + O_A;
    float* pAtr = sh + O_ATR;
    float* pCm  = sh + O_CM;
    float* pCtr = sh + O_CTR;
    float* zc   = sh + O_ZC;
    float* tmpM = sh + O_TMP;
    float* pPp  = sh + O_PP;
    float* pCPm = sh + O_CPM;
    float* aug0 = sh + O_AUG0;
    float* aug1 = sh + O_AUG1;
    float* fcS  = sh + O_FCS;
    float* fmS  = sh + O_FMS;
    float* zm   = sh + O_ZM;
    float* zm2  = sh + O_ZM2;
    float* alB  = sh + O_AL;
    float* suB  = sh + O_SU;
    float* saB  = sh + O_SA;
    float* apred= sh + O_AP;
    float* dz   = sh + O_DZ;
    float* qd   = sh + O_QD;
    float* rd   = sh + O_RD;

    const int tid = threadIdx.x;
    const int b   = blockIdx.x;
    const int i16 = tid >> 4;          // 0..31 (float2 maps)
    const int j2  = (tid & 15) << 1;
    const int i4  = tid >> 3;          // 0..31 for tid<256 (float4 maps)
    const int j4  = (tid & 7) << 2;    // 0,4..28

    // ---- preload constants, noise diagonals, t=0 inputs, init state ----
    for (int idx = tid; idx < 8192; idx += NT) sAm[idx] = g_A[idx];
    for (int idx = tid; idx < 8192; idx += NT) sBm[idx] = g_B[idx];
    for (int idx = tid; idx < 4096; idx += NT) sCm[idx] = g_C[idx];
    if (tid < 32) qd[tid] = expf(g_lQ[tid]);
    if (tid < 16) rd[tid] = expf(g_lR[tid]);
    {
        const size_t ib0 = (size_t)b * TLEN;
        if (tid < 8)  alB[tid] = g_alpha[ib0 * 8  + tid];
        if (tid < 32) suB[tid] = g_u    [ib0 * 32 + tid];
        if (tid < 16) saB[tid] = g_a    [ib0 * 16 + tid];
        if (tid < 32) zm[tid] = g_z0m[tid];
        float2 v = make_float2(0.f, 0.f);
        if (i16 == j2)          v.x = expf(g_z0lv[i16]);
        else if (i16 == j2 + 1) v.y = expf(g_z0lv[i16]);
        *(float2*)(zc + i16 * LD + j2) = v;
    }
    __syncthreads();

    // =============== FORWARD FILTER ===============
    #pragma unroll 1
    for (int t = 0; t < TLEN; ++t) {
        const size_t ib = (size_t)b * TLEN + t;
        const int pb = t & 1, nb = pb ^ 1;
        const bool hasnext = (t + 1 < TLEN);

        float pfa = 0.f, pfu = 0.f, pfo = 0.f;
        if (hasnext) {
            if (tid < 8)  pfa = g_alpha[(ib + 1) * 8  + tid];
            if (tid < 32) pfu = g_u    [(ib + 1) * 32 + tid];
            if (tid < 16) pfo = g_a    [(ib + 1) * 16 + tid];
        }

        // ---- P0: mixtures A, A^T, B(tmpM), C, C^T ----
        {
            const float* al = alB + pb * 8;
            float2 aa = make_float2(0.f, 0.f);
            float2 bb = make_float2(0.f, 0.f);
            #pragma unroll
            for (int k = 0; k < 8; ++k) {
                const float w = al[k];
                float2 m = *(const float2*)(sAm + k * 1024 + i16 * 32 + j2);
                aa.x = fmaf(w, m.x, aa.x); aa.y = fmaf(w, m.y, aa.y);
                m = *(const float2*)(sBm + k * 1024 + i16 * 32 + j2);
                bb.x = fmaf(w, m.x, bb.x); bb.y = fmaf(w, m.y, bb.y);
            }
            *(float2*)(pA + i16 * LD + j2) = aa;
            pAtr[(j2 + 0) * LD + i16] = aa.x;
            pAtr[(j2 + 1) * LD + i16] = aa.y;
            *(float2*)(tmpM + i16 * LD + j2) = bb;
            if (tid < 256) {
                float2 cc = make_float2(0.f, 0.f);
                #pragma unroll
                for (int k = 0; k < 8; ++k) {
                    const float w = al[k];
                    float2 m = *(const float2*)(sCm + k * 512 + i16 * 32 + j2);
                    cc.x = fmaf(w, m.x, cc.x); cc.y = fmaf(w, m.y, cc.y);
                }
                *(float2*)(pCm + i16 * LD + j2) = cc;
                pCtr[(j2 + 0) * LDCT + i16] = cc.x;
                pCtr[(j2 + 1) * LDCT + i16] = cc.y;
            }
        }
        __syncthreads();

        if (t > 0) {
            // ---- P1: Pp = A zc (256 thr) ; zm2 = A zm + B u (32 thr) ----
            if (tid < 256) {
                float4 acc = mm4(pA + i4 * LD, zc, LD, j4);
                *(float4*)(pPp + i4 * LD + j4) = acc;
            } else if (tid >= 480) {
                const int i = tid - 480;
                const float* su = suB + pb * 32;
                float4 s4 = make_float4(0.f, 0.f, 0.f, 0.f);
                #pragma unroll
                for (int k0 = 0; k0 < 32; k0 += 4) {
                    float4 m4 = *(const float4*)(tmpM + i * LD + k0);
                    float4 v4 = *(const float4*)(su + k0);
                    FMA4L(s4, m4, v4);
                    m4 = *(const float4*)(pA + i * LD + k0);
                    v4 = *(const float4*)(zm + k0);
                    FMA4L(s4, m4, v4);
                }
                zm2[i] = (s4.x + s4.y) + (s4.z + s4.w);
            }
            __syncthreads();
            // ---- P2: zc = Pp A^T + Q ; zm = zm2 ----
            if (tid < 256) {
                float4 acc = mm4(pPp + i4 * LD, pAtr, LD, j4);
                int d = i4 - j4;
                if (d >= 0 && d < 4) ((float*)&acc)[d] += qd[i4];
                *(float4*)(zc + i4 * LD + j4) = acc;
            } else if (tid >= 480) {
                zm[tid - 480] = zm2[tid - 480];
            }
            __syncthreads();
        }

        // ---- P3: M = C zc (128 thr) ; apred = C zm (16 thr) ----
        if (tid < 128) {
            float4 acc = mm4(pCm + i4 * LD, zc, LD, j4);
            *(float4*)(pCPm + i4 * LD + j4) = acc;
        } else if (tid >= 496) {
            const int i = tid - 496;
            float4 s4 = make_float4(0.f, 0.f, 0.f, 0.f);
            #pragma unroll
            for (int k0 = 0; k0 < 32; k0 += 4) {
                float4 m4 = *(const float4*)(pCm + i * LD + k0);
                float4 v4 = *(const float4*)(zm + k0);
                FMA4L(s4, m4, v4);
            }
            apred[i] = (s4.x + s4.y) + (s4.z + s4.w);
        }
        __syncthreads();

        // ---- P4: aug0 = [S | M], dz = a - apred; store prefetched inputs ----
        if (tid < 64) {
            const int i = tid >> 2, j0 = (tid & 3) << 2;
            float4 acc = mm4(pCPm + i * LD, pCtr, LDCT, j0);
            int d = i - j0;
            if (d >= 0 && d < 4) ((float*)&acc)[d] += rd[i];
            *(float4*)(aug0 + i * LDA + j0) = acc;
        } else if (tid >= 128 && tid < 144) {
            const int j = tid - 128;
            dz[j] = saB[pb * 16 + j] - apred[j];
        } else if (tid >= 256 && tid < 384) {
            const int idx = tid - 256;
            const int i = idx >> 3, j0 = (idx & 7) << 2;
            *(float4*)(aug0 + i * LDA + 16 + j0) = *(const float4*)(pCPm + i * LD + j0);
        }
        if (hasnext) {
            if (tid < 8)  alB[nb * 8  + tid] = pfa;
            if (tid < 32) suB[nb * 32 + tid] = pfu;
            if (tid < 16) saB[nb * 16 + tid] = pfo;
        }
        __syncthreads();

        // ---- GJ: 16 pivots, 4 per phase (4 barriers) ----
        {
            const int gi = tid >> 5;       // 0..15
            const int gj = tid & 31;       // col gj; +32 if gj<16
            float* Asrc = aug0; float* Adst = aug1;
            #pragma unroll 1
            for (int pp = 0; pp < 4; ++pp) {
                GJ4PRE(Asrc, gi, pp << 2);
                GJ4COL(Adst, Asrc, gi, gj);
                if (gj < 16) GJ4COL(Adst, Asrc, gi, gj + 32);
                float* tsw = Asrc; Asrc = Adst; Adst = tsw;
                __syncthreads();
            }
        }
        // Kg^T in aug0 cols 16..47

        // ---- P13: measurement update + filtered output ----
        {
            const size_t ob = ib * 2112;
            {   // zm += Kg dz via width-16 shfl (all 512 threads, row = i16)
                int lane16 = tid & 15;
                float v = aug0[lane16 * LDA + 16 + i16] * dz[lane16];
                #pragma unroll
                for (int off = 8; off; off >>= 1)
                    v += __shfl_xor_sync(0xffffffffu, v, off, 16);
                if (lane16 == 0) {
                    float nm = zm[i16] + v;
                    zm[i16] = nm;
                    out[ob + i16] = nm;
                    if (t == TLEN - 1) out[ob + 1056 + i16] = nm;
                }
            }
            if (tid < 256) {
                float4 acc = *(const float4*)(zc + i4 * LD + j4);
                #pragma unroll
                for (int r = 0; r < 16; ++r) {
                    float kv = aug0[r * LDA + 16 + i4];
                    float4 mv = *(const float4*)(pCPm + r * LD + j4);
                    acc.x = fmaf(-kv, mv.x, acc.x);
                    acc.y = fmaf(-kv, mv.y, acc.y);
                    acc.z = fmaf(-kv, mv.z, acc.z);
                    acc.w = fmaf(-kv, mv.w, acc.w);
                }
                *(float4*)(zc + i4 * LD + j4) = acc;
                *(float4*)(out + ob + 32 + i4 * 32 + j4) = acc;
                if (t == TLEN - 1) *(float4*)(out + ob + 1088 + i4 * 32 + j4) = acc;
            }
        }
        // no trailing barrier: next P0 touches disjoint smem; P0-end barrier orders zm/zc
    }

    // =============== BACKWARD RTS SMOOTHER ===============
    __syncthreads();
    {   // preload buffers for first backward iteration (t = TLEN-2)
        const size_t ibl = (size_t)b * TLEN + (TLEN - 1);
        const size_t ibp = (size_t)b * TLEN + (TLEN - 2);
        const int mb0 = (TLEN - 1) & 1;   // 1
        const int pb0 = (TLEN - 2) & 1;   // 0
        if (tid < 8)  alB[mb0 * 8  + tid] = g_alpha[ibl * 8  + tid];
        if (tid < 32) suB[mb0 * 32 + tid] = g_u    [ibl * 32 + tid];
        if (tid < 32) fmS[pb0 * 32 + tid] = out[ibp * 2112 + tid];
        *(float2*)(fcS + pb0 * (32 * LD) + i16 * LD + j2) =
            *(const float2*)(out + ibp * 2112 + 32 + i16 * 32 + j2);
    }
    __syncthreads();

    #pragma unroll 1
    for (int t = TLEN - 2; t >= 0; --t) {
        const size_t ib = (size_t)b * TLEN + t;
        const size_t ob = ib * 2112;
        const int pb = t & 1;          // fm/fc parity
        const int mb = (t + 1) & 1;    // alpha/u parity
        const bool hasprev = (t > 0);
        float* fcSp = fcS + pb * (32 * LD);
        float* fmSp = fmS + pb * 32;

        float pfa = 0.f, pfu = 0.f, pfm = 0.f;
        float2 pfc = make_float2(0.f, 0.f);
        if (tid < 8)  pfa = g_alpha[ib * 8  + tid];
        if (tid < 32) pfu = g_u    [ib * 32 + tid];
        if (hasprev) {
            const size_t obp = (ib - 1) * 2112;
            if (tid < 32) pfm = out[obp + tid];
            pfc = *(const float2*)(out + obp + 32 + i16 * 32 + j2);
        }

        // ---- P0: mixtures A, A^T, B(tmpM) for step t+1 ----
        {
            const float* al = alB + mb * 8;
            float2 aa = make_float2(0.f, 0.f);
            float2 bb = make_float2(0.f, 0.f);
            #pragma unroll
            for (int k = 0; k < 8; ++k) {
                const float w = al[k];
                float2 m = *(const float2*)(sAm + k * 1024 + i16 * 32 + j2);
                aa.x = fmaf(w, m.x, aa.x); aa.y = fmaf(w, m.y, aa.y);
                m = *(const float2*)(sBm + k * 1024 + i16 * 32 + j2);
                bb.x = fmaf(w, m.x, bb.x); bb.y = fmaf(w, m.y, bb.y);
            }
            *(float2*)(pA + i16 * LD + j2) = aa;
            pAtr[(j2 + 0) * LD + i16] = aa.x;
            pAtr[(j2 + 1) * LD + i16] = aa.y;
            *(float2*)(tmpM + i16 * LD + j2) = bb;
        }
        __syncthreads();

        // ---- P1: N = A fc -> aug0 cols 32..63 (256 thr) ; dz (32 thr) ----
        if (tid < 256) {
            float4 acc = mm4(pA + i4 * LD, fcSp, LD, j4);
            *(float4*)(aug0 + i4 * LDA + 32 + j4) = acc;
        } else if (tid >= 480) {
            const int i = tid - 480;
            const float* su = suB + mb * 32;
            float4 s4 = make_float4(0.f, 0.f, 0.f, 0.f);
            #pragma unroll
            for (int k0 = 0; k0 < 32; k0 += 4) {
                float4 m4 = *(const float4*)(tmpM + i * LD + k0);
                float4 v4 = *(const float4*)(su + k0);
                FMA4L(s4, m4, v4);
                m4 = *(const float4*)(pA + i * LD + k0);
                v4 = *(const float4*)(fmSp + k0);
                FMA4L(s4, m4, v4);
            }
            dz[i] = zm[i] - ((s4.x + s4.y) + (s4.z + s4.w));
        }
        __syncthreads();

        // ---- P2: P_pred = N A^T + Q -> pPp and aug0 left; store prefetch ----
        if (tid < 256) {
            float4 acc = mm4(aug0 + i4 * LDA + 32, pAtr, LD, j4);
            int d = i4 - j4;
            if (d >= 0 && d < 4) ((float*)&acc)[d] += qd[i4];
            *(float4*)(pPp + i4 * LD + j4) = acc;
            *(float4*)(aug0 + i4 * LDA + j4) = acc;
        }
        if (tid < 8)  alB[pb * 8  + tid] = pfa;
        if (tid < 32) suB[pb * 32 + tid] = pfu;
        if (hasprev) {
            if (tid < 32) fmS[mb * 32 + tid] = pfm;
            *(float2*)(fcS + mb * (32 * LD) + i16 * LD + j2) = pfc;
        }
        __syncthreads();

        // ---- GJ: 32 pivots, 4 per phase (8 barriers) ----
        {
            const int gi = tid >> 4;       // 0..31
            const int gj = tid & 15;       // cols gj, +16, +32, +48
            float* Asrc = aug0; float* Adst = aug1;
            #pragma unroll 1
            for (int pp = 0; pp < 8; ++pp) {
                GJ4PRE(Asrc, gi, pp << 2);
                GJ4COL(Adst, Asrc, gi, gj);
                GJ4COL(Adst, Asrc, gi, gj + 16);
                GJ4COL(Adst, Asrc, gi, gj + 32);
                GJ4COL(Adst, Asrc, gi, gj + 48);
                float* tsw = Asrc; Asrc = Adst; Adst = tsw;
                __syncthreads();
            }
        }
        // Y = Ppred^-1 N = J^T in aug0 cols 32..63

        // ---- P19: zs = fm + Y^T dz (shfl) ; D = Ps - Ppred -> tmpM ----
        {
            int lane = tid & 31;
            int o0 = (tid >> 5) << 1;   // each warp 2 outputs
            float v0 = aug0[lane * LDA + 32 + o0]     * dz[lane];
            float v1 = aug0[lane * LDA + 32 + o0 + 1] * dz[lane];
            #pragma unroll
            for (int off = 16; off; off >>= 1) {
                v0 += __shfl_xor_sync(0xffffffffu, v0, off);
                v1 += __shfl_xor_sync(0xffffffffu, v1, off);
            }
            if (lane == 0) {
                float nm0 = fmSp[o0] + v0;
                float nm1 = fmSp[o0 + 1] + v1;
                zm[o0] = nm0; zm[o0 + 1] = nm1;
                out[ob + 1056 + o0] = nm0;
                out[ob + 1056 + o0 + 1] = nm1;
            }
            float2 a  = *(const float2*)(zc  + i16 * LD + j2);
            float2 p2 = *(const float2*)(pPp + i16 * LD + j2);
            a.x -= p2.x; a.y -= p2.y;
            *(float2*)(tmpM + i16 * LD + j2) = a;
        }
        __syncthreads();

        // ---- P20: W = D Y -> pPp (256 thr) ----
        if (tid < 256) {
            float4 acc = mm4(tmpM + i4 * LD, aug0 + 32, LDA, j4);
            *(float4*)(pPp + i4 * LD + j4) = acc;
        }
        __syncthreads();

        // ---- P21: Ps = fc + Y^T W -> zc, write sc (256 thr) ----
        if (tid < 256) {
            float4 acc = *(const float4*)(fcSp + i4 * LD + j4);
            #pragma unroll
            for (int k = 0; k < 32; ++k) {
                float yv = aug0[k * LDA + 32 + i4];
                float4 wv = *(const float4*)(pPp + k * LD + j4);
                FMA4S(acc, yv, wv);
            }
            *(float4*)(zc + i4 * LD + j4) = acc;
            *(float4*)(out + ob + 1088 + i4 * 32 + j4) = acc;
        }
        // no trailing barrier: next P0 writes pA/pAtr/tmpM, none read in P21
    }
}

extern "C" void kernel_launch(void* const* d_in, const int* in_sizes, int n_in,
                              void* d_out, int out_size) {
    const float* g_a    = (const float*)d_in[0];
    const float* g_alpha= (const float*)d_in[1];
    const float* g_u    = (const float*)d_in[2];
    const float* g_A    = (const float*)d_in[3];
    const float* g_B    = (const float*)d_in[4];
    const float* g_C    = (const float*)d_in[5];
    const float* g_lQ   = (const float*)d_in[6];
    const float* g_lR   = (const float*)d_in[7];
    const float* g_z0m  = (const float*)d_in[8];
    const float* g_z0lv = (const float*)d_in[9];
    float* out = (float*)d_out;
    int B = in_sizes[0] / (TLEN * 16);
    size_t smem = SMEM_FLOATS * sizeof(float);
    cudaFuncSetAttribute(lgssm_kernel, cudaFuncAttributeMaxDynamicSharedMemorySize, (int)smem);
    lgssm_kernel<<<B, NT, smem>>>(g_a, g_alpha, g_u, g_A, g_B, g_C,
                                  g_lQ, g_lR, g_z0m, g_z0lv, out);
}